// round 5
// baseline (speedup 1.0000x reference)
#include <cuda_runtime.h>
#include <cuda_bf16.h>
#include <math.h>
#include <stdint.h>

#define NBATCH 32
#define SLEN   2048
#define NIN    128
#define HSZ    256
#define G4     1024
#define NTOK   (NBATCH * SLEN)   // 65536
#define QDIM   16
#define MMEM   64

// ---------------- static scratch (allocation-free) ----------------
__device__ float g_xg[(size_t)NTOK * G4];   // xg for the current layer
__device__ float g_h [(size_t)NTOK * HSZ];  // h1, then lstm_out
__device__ float g_mv[MMEM * HSZ];          // mem_vals @ Wq^T
__device__ float g_w [NTOK * 4];            // per-token scaled top3 weights
__device__ int   g_idx[NTOK * 4];           // per-token top3 indices

// =================================================================
// Tiled SIMT GEMM: C[m,n] = sum_k A[m,k]*B[n,k] + bias1[n] + bias2[n]
// =================================================================
__global__ __launch_bounds__(256) void gemm_bt_kernel(
    const float* __restrict__ A, int lda,
    const float* __restrict__ B, int ldb,
    float* __restrict__ C, int ldc,
    int K,
    const float* __restrict__ bias1, const float* __restrict__ bias2)
{
    __shared__ __align__(16) float As[16][68];
    __shared__ __align__(16) float Bs[16][68];
    int tid = threadIdx.x;
    int bm = blockIdx.y * 64, bn = blockIdx.x * 64;
    int lr = tid >> 2, lk = (tid & 3) * 4;
    int tx = tid & 15, ty = tid >> 4;
    float acc[4][4] = {};
    const float* Ap = A + (size_t)(bm + lr) * lda + lk;
    const float* Bp = B + (size_t)(bn + lr) * ldb + lk;

    for (int k0 = 0; k0 < K; k0 += 16) {
        float4 av = *(const float4*)(Ap + k0);
        float4 bv = *(const float4*)(Bp + k0);
        As[lk + 0][lr] = av.x; As[lk + 1][lr] = av.y;
        As[lk + 2][lr] = av.z; As[lk + 3][lr] = av.w;
        Bs[lk + 0][lr] = bv.x; Bs[lk + 1][lr] = bv.y;
        Bs[lk + 2][lr] = bv.z; Bs[lk + 3][lr] = bv.w;
        __syncthreads();
#pragma unroll
        for (int kk = 0; kk < 16; kk++) {
            float4 a4 = *(const float4*)&As[kk][ty * 4];
            float4 b4 = *(const float4*)&Bs[kk][tx * 4];
            float a[4] = {a4.x, a4.y, a4.z, a4.w};
            float b[4] = {b4.x, b4.y, b4.z, b4.w};
#pragma unroll
            for (int i = 0; i < 4; i++)
#pragma unroll
                for (int j = 0; j < 4; j++)
                    acc[i][j] = fmaf(a[i], b[j], acc[i][j]);
        }
        __syncthreads();
    }

    float bcol[4];
#pragma unroll
    for (int j = 0; j < 4; j++) {
        int n = bn + tx * 4 + j;
        float bv = 0.f;
        if (bias1) bv += bias1[n];
        if (bias2) bv += bias2[n];
        bcol[j] = bv;
    }
#pragma unroll
    for (int i = 0; i < 4; i++) {
        int m = bm + ty * 4 + i;
        float4 o;
        o.x = acc[i][0] + bcol[0];
        o.y = acc[i][1] + bcol[1];
        o.z = acc[i][2] + bcol[2];
        o.w = acc[i][3] + bcol[3];
        *(float4*)&C[(size_t)m * ldc + bn + tx * 4] = o;
    }
}

// =================================================================
// Output GEMM with fused quantum-memory epilogue
// =================================================================
__global__ __launch_bounds__(256) void out_gemm_kernel(
    const float* __restrict__ A, int lda,
    const float* __restrict__ B, int ldb,
    float* __restrict__ C, int ldc,
    int K,
    const float* __restrict__ bout,
    const float* __restrict__ cwp,
    const float* __restrict__ wts,
    const int*   __restrict__ idxs,
    const float* __restrict__ MV)
{
    __shared__ __align__(16) float As[16][68];
    __shared__ __align__(16) float Bs[16][68];
    int tid = threadIdx.x;
    int bm = blockIdx.y * 64, bn = blockIdx.x * 64;
    int lr = tid >> 2, lk = (tid & 3) * 4;
    int tx = tid & 15, ty = tid >> 4;
    float acc[4][4] = {};
    const float* Ap = A + (size_t)(bm + lr) * lda + lk;
    const float* Bp = B + (size_t)(bn + lr) * ldb + lk;

    for (int k0 = 0; k0 < K; k0 += 16) {
        float4 av = *(const float4*)(Ap + k0);
        float4 bv = *(const float4*)(Bp + k0);
        As[lk + 0][lr] = av.x; As[lk + 1][lr] = av.y;
        As[lk + 2][lr] = av.z; As[lk + 3][lr] = av.w;
        Bs[lk + 0][lr] = bv.x; Bs[lk + 1][lr] = bv.y;
        Bs[lk + 2][lr] = bv.z; Bs[lk + 3][lr] = bv.w;
        __syncthreads();
#pragma unroll
        for (int kk = 0; kk < 16; kk++) {
            float4 a4 = *(const float4*)&As[kk][ty * 4];
            float4 b4 = *(const float4*)&Bs[kk][tx * 4];
            float a[4] = {a4.x, a4.y, a4.z, a4.w};
            float b[4] = {b4.x, b4.y, b4.z, b4.w};
#pragma unroll
            for (int i = 0; i < 4; i++)
#pragma unroll
                for (int j = 0; j < 4; j++)
                    acc[i][j] = fmaf(a[i], b[j], acc[i][j]);
        }
        __syncthreads();
    }

    float cw = *cwp;
#pragma unroll
    for (int i = 0; i < 4; i++) {
        int m = bm + ty * 4 + i;
        float w0 = wts[m * 4 + 0], w1 = wts[m * 4 + 1], w2 = wts[m * 4 + 2];
        int   i0 = idxs[m * 4 + 0], i1 = idxs[m * 4 + 1], i2 = idxs[m * 4 + 2];
        const float* mv0 = MV + (size_t)i0 * HSZ;
        const float* mv1 = MV + (size_t)i1 * HSZ;
        const float* mv2 = MV + (size_t)i2 * HSZ;
        float out4[4];
#pragma unroll
        for (int j = 0; j < 4; j++) {
            int n = bn + tx * 4 + j;
            float v = cw * acc[i][j] + bout[n];
            v = fmaf(w0, mv0[n], v);
            v = fmaf(w1, mv1[n], v);
            v = fmaf(w2, mv2[n], v);
            out4[j] = v;
        }
        *(float4*)&C[(size_t)m * ldc + bn + tx * 4] =
            make_float4(out4[0], out4[1], out4[2], out4[3]);
    }
}

// =================================================================
// MV[m][h] = sum_h' mem_vals[m][h'] * W_out[h][256 + h']
// =================================================================
__global__ void mv_kernel(const float* __restrict__ vals,
                          const float* __restrict__ Wout,
                          float* __restrict__ mv)
{
    int m = blockIdx.x, h = threadIdx.x;
    const float* vrow = vals + (size_t)m * HSZ;
    const float* wrow = Wout + (size_t)h * 2 * HSZ + HSZ;
    float acc = 0.f;
#pragma unroll 8
    for (int k = 0; k < HSZ; k++) acc = fmaf(vrow[k], wrow[k], acc);
    mv[(size_t)m * HSZ + h] = acc;
}

// =================================================================
// LSTM scan helpers
// =================================================================
__device__ __forceinline__ unsigned mapa_u32(unsigned addr, unsigned rank) {
    unsigned r;
    asm("mapa.shared::cluster.u32 %0, %1, %2;" : "=r"(r) : "r"(addr), "r"(rank));
    return r;
}
__device__ __forceinline__ void st_cluster_f32(unsigned addr, float v) {
    asm volatile("st.shared::cluster.f32 [%0], %1;" :: "r"(addr), "f"(v) : "memory");
}
__device__ __forceinline__ void cluster_sync_all() {
    asm volatile("barrier.cluster.arrive.aligned;" ::: "memory");
    asm volatile("barrier.cluster.wait.aligned;" ::: "memory");
}
__device__ __forceinline__ void ffma2(unsigned long long& acc,
                                      unsigned long long a,
                                      unsigned long long b) {
    asm("fma.rn.f32x2 %0, %1, %2, %3;" : "=l"(acc) : "l"(a), "l"(b), "l"(acc));
}
__device__ __forceinline__ float f2lo(unsigned long long v) {
    return __uint_as_float((unsigned)(v & 0xffffffffull));
}
__device__ __forceinline__ float f2hi(unsigned long long v) {
    return __uint_as_float((unsigned)(v >> 32));
}
__device__ __forceinline__ void mbar_init(unsigned addr, unsigned cnt) {
    asm volatile("mbarrier.init.shared.b64 [%0], %1;" :: "r"(addr), "r"(cnt) : "memory");
}
__device__ __forceinline__ void mbar_arrive_cluster(unsigned addr) {
    asm volatile("mbarrier.arrive.shared::cluster.b64 _, [%0];" :: "r"(addr) : "memory");
}
__device__ __forceinline__ void mbar_wait_parity(unsigned addr, unsigned parity) {
    unsigned done;
    asm volatile(
        "{\n\t.reg .pred p;\n\t"
        "mbarrier.try_wait.parity.acquire.cta.shared::cta.b64 p, [%1], %2;\n\t"
        "selp.b32 %0, 1, 0, p;\n\t}"
        : "=r"(done) : "r"(addr), "r"(parity) : "memory");
    if (!done) {
        asm volatile(
            "{\n\t.reg .pred P1;\n\t"
            "W_%=:\n\t"
            "mbarrier.try_wait.parity.acquire.cta.shared::cta.b64 P1, [%0], %1, 0x989680;\n\t"
            "@P1 bra.uni D_%=;\n\t"
            "bra.uni W_%=;\n\t"
            "D_%=:\n\t}"
            :: "r"(addr), "r"(parity) : "memory");
    }
}
__device__ __forceinline__ float sigmoid_f(float x) {
    return __fdividef(1.f, 1.f + __expf(-x));
}
__device__ __forceinline__ float tanh_f(float x) {
    return fmaf(-2.f, __fdividef(1.f, 1.f + __expf(2.f * x)), 1.f);
}

// =================================================================
// LSTM scan: 16 clusters x 8 CTAs, 2 batch rows per cluster.
// 512 threads: lr = tid>>2 (128 gate rows), kc = tid&3 (k-quarter).
// Weights: 32 f32x2 regs/thread. h exchanged via st.shared::cluster
// push; per-step sync via mbarrier (arrive-count 8, one per CTA).
// =================================================================
__global__ __launch_bounds__(512, 1) __cluster_dims__(8, 1, 1)
void lstm_scan_kernel(const float* __restrict__ xg,    // [32][2048][1024]
                      const float* __restrict__ Whh,   // [1024][256]
                      float* __restrict__ hout)        // [32][2048][256]
{
    __shared__ __align__(16) float hbuf[2][2][HSZ];  // parity, batch, k
    __shared__ float gbuf[2][128];
    __shared__ __align__(8) unsigned long long mbar_s;

    int tid = threadIdx.x;
    int crank = blockIdx.x & 7;
    int cid   = blockIdx.x >> 3;
    int b0 = cid * 2;
    int lr = tid >> 2;           // gate row in [0,128)
    int kc = tid & 3;            // k quarter
    int grow = (lr >> 5) * HSZ + crank * 32 + (lr & 31);

    // 64 weights -> 32 f32x2 registers
    unsigned long long w2[32];
    {
        const unsigned long long* wp =
            (const unsigned long long*)(Whh + (size_t)grow * HSZ + kc * 64);
#pragma unroll
        for (int i = 0; i < 32; i++) w2[i] = wp[i];
    }

    unsigned hb0 = (unsigned)__cvta_generic_to_shared(&hbuf[0][0][0]);
    unsigned mb0 = (unsigned)__cvta_generic_to_shared(&mbar_s);
    unsigned peer_h[8], peer_m[8];
#pragma unroll
    for (int p = 0; p < 8; p++) {
        peer_h[p] = mapa_u32(hb0, (unsigned)p);
        peer_m[p] = mapa_u32(mb0, (unsigned)p);
    }

    if (tid == 0) mbar_init(mb0, 8);
    for (int i = tid; i < 2 * 2 * HSZ; i += 512) ((float*)hbuf)[i] = 0.f;
    __syncthreads();
    cluster_sync_all();   // mbarriers + zeroed hbufs visible cluster-wide

    bool pw = tid < 64;                  // 2 batches x 32 columns
    int pb = tid >> 5, pj = tid & 31;
    float c_state = 0.f;
    float x0 = 0.f, x1 = 0.f, x2 = 0.f, x3 = 0.f;
    const float* xgb = xg;
    float* hob = hout;
    if (pw) {
        xgb = xg + (size_t)(b0 + pb) * SLEN * G4 + crank * 32 + pj;
        hob = hout + (size_t)(b0 + pb) * SLEN * HSZ + crank * 32 + pj;
        x0 = xgb[0]; x1 = xgb[256]; x2 = xgb[512]; x3 = xgb[768];
    }

    for (int t = 0; t < SLEN; t++) {
        int par = t & 1;
        const ulonglong2* hA = (const ulonglong2*)&hbuf[par][0][kc * 64];
        const ulonglong2* hB = (const ulonglong2*)&hbuf[par][1][kc * 64];
        unsigned long long a0 = 0ull, a1 = 0ull, c0 = 0ull, c1 = 0ull;
#pragma unroll
        for (int i = 0; i < 16; i++) {
            ulonglong2 va = hA[i];
            ulonglong2 vb = hB[i];
            ffma2(a0, w2[2 * i + 0], va.x);
            ffma2(a1, w2[2 * i + 1], va.y);
            ffma2(c0, w2[2 * i + 0], vb.x);
            ffma2(c1, w2[2 * i + 1], vb.y);
        }
        float sa = (f2lo(a0) + f2hi(a0)) + (f2lo(a1) + f2hi(a1));
        float sb = (f2lo(c0) + f2hi(c0)) + (f2lo(c1) + f2hi(c1));
        sa += __shfl_xor_sync(0xffffffffu, sa, 1);
        sa += __shfl_xor_sync(0xffffffffu, sa, 2);
        sb += __shfl_xor_sync(0xffffffffu, sb, 1);
        sb += __shfl_xor_sync(0xffffffffu, sb, 2);
        if (kc == 0) { gbuf[0][lr] = sa; gbuf[1][lr] = sb; }
        __syncthreads();   // all hbuf[par] reads + gbuf writes done

        if (pw) {
            float gi = gbuf[pb][      pj] + x0;
            float gf = gbuf[pb][ 32 + pj] + x1;
            float gg = gbuf[pb][ 64 + pj] + x2;
            float go = gbuf[pb][ 96 + pj] + x3;
            float si = sigmoid_f(gi);
            float sf = sigmoid_f(gf);
            float so = sigmoid_f(go);
            float tg = tanh_f(gg);
            c_state = fmaf(sf, c_state, si * tg);
            float h = so * tanh_f(c_state);
            hob[(size_t)t * HSZ] = h;
            unsigned off = (unsigned)((((par ^ 1) * 2 + pb) * HSZ +
                                       crank * 32 + pj) * 4);
#pragma unroll
            for (int p = 0; p < 8; p++) st_cluster_f32(peer_h[p] + off, h);
            int tn = (t + 1 < SLEN) ? (t + 1) : t;
            const float* xp = xgb + (size_t)tn * G4;
            x0 = xp[0]; x1 = xp[256]; x2 = xp[512]; x3 = xp[768];
            asm volatile("bar.sync 1, 64;" ::: "memory");  // pw stores done
            if (tid == 0) {
                asm volatile("fence.acq_rel.cluster;" ::: "memory");
#pragma unroll
                for (int p = 0; p < 8; p++) mbar_arrive_cluster(peer_m[p]);
            }
        }
        mbar_wait_parity(mb0, (unsigned)(t & 1));
    }
    cluster_sync_all();   // no CTA exits while peers may still write our smem
}

// =================================================================
// kNN over quantum memory: per token -> 3 indices + 3 scaled weights
// =================================================================
__global__ __launch_bounds__(256) void knn_kernel(
    const float* __restrict__ lstm,
    const float* __restrict__ Wcq, const float* __restrict__ bcq,
    const float* __restrict__ keys, const float* __restrict__ qwp,
    float* __restrict__ wout, int* __restrict__ idxout)
{
    __shared__ float sWcq[QDIM][HSZ];
    __shared__ float skn[MMEM][QDIM];
    __shared__ __align__(16) float sh[8][HSZ];
    __shared__ float sq[8][QDIM];
    __shared__ float ssims[8][MMEM];
    int tid = threadIdx.x;
    for (int i = tid; i < QDIM * HSZ; i += 256)
        sWcq[i >> 8][i & 255] = Wcq[i];
    if (tid < MMEM) {
        float kv[QDIM]; float nrm = 0.f;
#pragma unroll
        for (int d = 0; d < QDIM; d++) { kv[d] = keys[tid * QDIM + d]; nrm += kv[d] * kv[d]; }
        float inv = 1.f / (sqrtf(nrm) + 1e-8f);
#pragma unroll
        for (int d = 0; d < QDIM; d++) skn[tid][d] = kv[d] * inv;
    }
    __syncthreads();

    int wid = tid >> 5, lane = tid & 31;
    int token = blockIdx.x * 8 + wid;
    const float* hrow = lstm + (size_t)token * HSZ;
    for (int i = lane; i < HSZ / 4; i += 32)
        ((float4*)sh[wid])[i] = ((const float4*)hrow)[i];
    __syncwarp();
    if (lane < QDIM) {
        float acc = bcq[lane];
#pragma unroll 8
        for (int k = 0; k < HSZ; k++) acc = fmaf(sWcq[lane][k], sh[wid][k], acc);
        sq[wid][lane] = tanhf(acc);
    }
    __syncwarp();
    float qn[QDIM];
    {
        float nrm = 0.f;
#pragma unroll
        for (int d = 0; d < QDIM; d++) { float v = sq[wid][d]; nrm += v * v; }
        float inv = 1.f / (sqrtf(nrm) + 1e-8f);
#pragma unroll
        for (int d = 0; d < QDIM; d++) qn[d] = sq[wid][d] * inv;
    }
#pragma unroll
    for (int mm = 0; mm < 2; mm++) {
        int m = lane + mm * 32;
        float s = 0.f;
#pragma unroll
        for (int d = 0; d < QDIM; d++) s = fmaf(qn[d], skn[m][d], s);
        ssims[wid][m] = s;
    }
    __syncwarp();
    if (lane == 0) {
        float v0 = -1e30f, v1 = -1e30f, v2 = -1e30f;
        int i0 = 0, i1 = 0, i2 = 0;
        for (int m = 0; m < MMEM; m++) {
            float s = ssims[wid][m];
            if (s > v0)      { v2 = v1; i2 = i1; v1 = v0; i1 = i0; v0 = s; i0 = m; }
            else if (s > v1) { v2 = v1; i2 = i1; v1 = s;  i1 = m; }
            else if (s > v2) { v2 = s;  i2 = m; }
        }
        float tot = v0 + v1 + v2;
        float qw = *qwp;
        float sc = (tot > 0.f) ? (qw / tot) : 0.f;
        wout[token * 4 + 0] = v0 * sc;
        wout[token * 4 + 1] = v1 * sc;
        wout[token * 4 + 2] = v2 * sc;
        idxout[token * 4 + 0] = i0;
        idxout[token * 4 + 1] = i1;
        idxout[token * 4 + 2] = i2;
    }
}

// =================================================================
extern "C" void kernel_launch(void* const* d_in, const int* in_sizes, int n_in,
                              void* d_out, int out_size) {
    const float* x      = (const float*)d_in[0];
    const float* W_ih0  = (const float*)d_in[1];
    const float* W_hh0  = (const float*)d_in[2];
    const float* b_ih0  = (const float*)d_in[3];
    const float* b_hh0  = (const float*)d_in[4];
    const float* W_ih1  = (const float*)d_in[5];
    const float* W_hh1  = (const float*)d_in[6];
    const float* b_ih1  = (const float*)d_in[7];
    const float* b_hh1  = (const float*)d_in[8];
    const float* W_cq   = (const float*)d_in[9];
    const float* b_cq   = (const float*)d_in[10];
    const float* mkeys  = (const float*)d_in[11];
    const float* mvals  = (const float*)d_in[12];
    const float* W_out  = (const float*)d_in[13];
    const float* b_out  = (const float*)d_in[14];
    const float* cw     = (const float*)d_in[15];
    const float* qw     = (const float*)d_in[16];
    float* out = (float*)d_out;

    float* xg  = nullptr; cudaGetSymbolAddress((void**)&xg,  g_xg);
    float* hbf = nullptr; cudaGetSymbolAddress((void**)&hbf, g_h);
    float* mv  = nullptr; cudaGetSymbolAddress((void**)&mv,  g_mv);
    float* wts = nullptr; cudaGetSymbolAddress((void**)&wts, g_w);
    int*   idx = nullptr; cudaGetSymbolAddress((void**)&idx, g_idx);

    // #1
    mv_kernel<<<MMEM, HSZ>>>(mvals, W_out, mv);

    // layer 0 input GEMM split in two (#2, #3) so scan #6 is ncu's capture
    {
        dim3 grid(G4 / 64, NTOK / 128);
        gemm_bt_kernel<<<grid, 256>>>(x, NIN, W_ih0, NIN, xg, G4, NIN,
                                      b_ih0, b_hh0);
        gemm_bt_kernel<<<grid, 256>>>(x + (size_t)(NTOK / 2) * NIN, NIN,
                                      W_ih0, NIN,
                                      xg + (size_t)(NTOK / 2) * G4, G4, NIN,
                                      b_ih0, b_hh0);
    }
    // #4
    lstm_scan_kernel<<<128, 512>>>(xg, W_hh0, hbf);

    // #5
    {
        dim3 grid(G4 / 64, NTOK / 64);
        gemm_bt_kernel<<<grid, 256>>>(hbf, HSZ, W_ih1, HSZ, xg, G4, HSZ,
                                      b_ih1, b_hh1);
    }
    // #6  (ncu -s 5 -c 1 capture slot)
    lstm_scan_kernel<<<128, 512>>>(xg, W_hh1, hbf);

    // #7
    knn_kernel<<<NTOK / 8, 256>>>(hbf, W_cq, b_cq, mkeys, qw, wts, idx);

    // #8
    {
        dim3 grid(HSZ / 64, NTOK / 64);
        out_gemm_kernel<<<grid, 256>>>(hbf, HSZ, W_out, 2 * HSZ, out, HSZ, HSZ,
                                       b_out, cw, wts, idx, mv);
    }
}

// round 8
// speedup vs baseline: 2.4183x; 2.4183x over previous
#include <cuda_runtime.h>
#include <cuda_bf16.h>
#include <cuda_fp16.h>
#include <math.h>
#include <stdint.h>

#define NBATCH 32
#define SLEN   2048
#define NIN    128
#define HSZ    256
#define G4     1024
#define NTOK   (NBATCH * SLEN)   // 65536
#define QDIM   16
#define MMEM   64

// ---------------- static scratch (allocation-free) ----------------
__device__ float g_xg[(size_t)NTOK * G4];   // permuted xg for current layer
__device__ float g_h [(size_t)NTOK * HSZ];  // h1, then lstm_out
__device__ float g_mv[MMEM * HSZ];          // mem_vals @ Wq^T
__device__ float g_w [NTOK * 4];            // per-token scaled top3 weights
__device__ int   g_idx[NTOK * 4];           // per-token top3 indices
// permuted W_hh split: w1 = fp16(w), w2s = fp16((w - w1) * 2^11)
__device__ __half g_W1_0[G4 * HSZ];
__device__ __half g_W2_0[G4 * HSZ];
__device__ __half g_W1_1[G4 * HSZ];
__device__ __half g_W2_1[G4 * HSZ];
__device__ float g_Wp_ih0[G4 * NIN];
__device__ float g_Wp_ih1[G4 * HSZ];
__device__ float g_bp0[G4];
__device__ float g_bp1[G4];
// h stage: per cluster 3 matrices (h1,h2',h3') x 2 parity x 2048 u32 words
__device__ float g_hstage[2 * 3 * 2 * 2048];

// =================================================================
// Weight/bias permutation + fp16 hi/scaled-lo split for W_hh
// =================================================================
__global__ void prep_kernel(const float* __restrict__ Whh0,
                            const float* __restrict__ Whh1,
                            const float* __restrict__ Wih0,
                            const float* __restrict__ Wih1,
                            const float* __restrict__ bih0,
                            const float* __restrict__ bhh0,
                            const float* __restrict__ bih1,
                            const float* __restrict__ bhh1)
{
    int p = blockIdx.x;                   // permuted row 0..1023
    int src = (p & 3) * HSZ + (p >> 2);   // gate = p&3, hcol = p>>2
    int tid = threadIdx.x;
    for (int k = tid; k < HSZ; k += blockDim.x) {
        float v0 = Whh0[src * HSZ + k];
        __half a0 = __float2half_rn(v0);
        g_W1_0[p * HSZ + k] = a0;
        g_W2_0[p * HSZ + k] = __float2half_rn((v0 - __half2float(a0)) * 2048.f);
        float v1 = Whh1[src * HSZ + k];
        __half a1 = __float2half_rn(v1);
        g_W1_1[p * HSZ + k] = a1;
        g_W2_1[p * HSZ + k] = __float2half_rn((v1 - __half2float(a1)) * 2048.f);
        g_Wp_ih1[p * HSZ + k] = Wih1[src * HSZ + k];
    }
    for (int k = tid; k < NIN; k += blockDim.x)
        g_Wp_ih0[p * NIN + k] = Wih0[src * NIN + k];
    if (tid == 0) {
        g_bp0[p] = bih0[src] + bhh0[src];
        g_bp1[p] = bih1[src] + bhh1[src];
    }
}

// =================================================================
// Tiled SIMT GEMM: C[m,n] = sum_k A[m,k]*B[n,k] + bias[n]
// =================================================================
__global__ __launch_bounds__(256) void gemm_bt_kernel(
    const float* __restrict__ A, int lda,
    const float* __restrict__ B, int ldb,
    float* __restrict__ C, int ldc,
    int K,
    const float* __restrict__ bias1)
{
    __shared__ __align__(16) float As[16][68];
    __shared__ __align__(16) float Bs[16][68];
    int tid = threadIdx.x;
    int bm = blockIdx.y * 64, bn = blockIdx.x * 64;
    int lr = tid >> 2, lk = (tid & 3) * 4;
    int tx = tid & 15, ty = tid >> 4;
    float acc[4][4] = {};
    const float* Ap = A + (size_t)(bm + lr) * lda + lk;
    const float* Bp = B + (size_t)(bn + lr) * ldb + lk;

    for (int k0 = 0; k0 < K; k0 += 16) {
        float4 av = *(const float4*)(Ap + k0);
        float4 bv = *(const float4*)(Bp + k0);
        As[lk + 0][lr] = av.x; As[lk + 1][lr] = av.y;
        As[lk + 2][lr] = av.z; As[lk + 3][lr] = av.w;
        Bs[lk + 0][lr] = bv.x; Bs[lk + 1][lr] = bv.y;
        Bs[lk + 2][lr] = bv.z; Bs[lk + 3][lr] = bv.w;
        __syncthreads();
#pragma unroll
        for (int kk = 0; kk < 16; kk++) {
            float4 a4 = *(const float4*)&As[kk][ty * 4];
            float4 b4 = *(const float4*)&Bs[kk][tx * 4];
            float a[4] = {a4.x, a4.y, a4.z, a4.w};
            float b[4] = {b4.x, b4.y, b4.z, b4.w};
#pragma unroll
            for (int i = 0; i < 4; i++)
#pragma unroll
                for (int j = 0; j < 4; j++)
                    acc[i][j] = fmaf(a[i], b[j], acc[i][j]);
        }
        __syncthreads();
    }

    float bcol[4];
#pragma unroll
    for (int j = 0; j < 4; j++)
        bcol[j] = bias1 ? bias1[bn + tx * 4 + j] : 0.f;
#pragma unroll
    for (int i = 0; i < 4; i++) {
        int m = bm + ty * 4 + i;
        float4 o;
        o.x = acc[i][0] + bcol[0];
        o.y = acc[i][1] + bcol[1];
        o.z = acc[i][2] + bcol[2];
        o.w = acc[i][3] + bcol[3];
        *(float4*)&C[(size_t)m * ldc + bn + tx * 4] = o;
    }
}

// =================================================================
// Output GEMM with fused quantum-memory epilogue
// =================================================================
__global__ __launch_bounds__(256) void out_gemm_kernel(
    const float* __restrict__ A, int lda,
    const float* __restrict__ B, int ldb,
    float* __restrict__ C, int ldc,
    int K,
    const float* __restrict__ bout,
    const float* __restrict__ cwp,
    const float* __restrict__ wts,
    const int*   __restrict__ idxs,
    const float* __restrict__ MV)
{
    __shared__ __align__(16) float As[16][68];
    __shared__ __align__(16) float Bs[16][68];
    int tid = threadIdx.x;
    int bm = blockIdx.y * 64, bn = blockIdx.x * 64;
    int lr = tid >> 2, lk = (tid & 3) * 4;
    int tx = tid & 15, ty = tid >> 4;
    float acc[4][4] = {};
    const float* Ap = A + (size_t)(bm + lr) * lda + lk;
    const float* Bp = B + (size_t)(bn + lr) * ldb + lk;

    for (int k0 = 0; k0 < K; k0 += 16) {
        float4 av = *(const float4*)(Ap + k0);
        float4 bv = *(const float4*)(Bp + k0);
        As[lk + 0][lr] = av.x; As[lk + 1][lr] = av.y;
        As[lk + 2][lr] = av.z; As[lk + 3][lr] = av.w;
        Bs[lk + 0][lr] = bv.x; Bs[lk + 1][lr] = bv.y;
        Bs[lk + 2][lr] = bv.z; Bs[lk + 3][lr] = bv.w;
        __syncthreads();
#pragma unroll
        for (int kk = 0; kk < 16; kk++) {
            float4 a4 = *(const float4*)&As[kk][ty * 4];
            float4 b4 = *(const float4*)&Bs[kk][tx * 4];
            float a[4] = {a4.x, a4.y, a4.z, a4.w};
            float b[4] = {b4.x, b4.y, b4.z, b4.w};
#pragma unroll
            for (int i = 0; i < 4; i++)
#pragma unroll
                for (int j = 0; j < 4; j++)
                    acc[i][j] = fmaf(a[i], b[j], acc[i][j]);
        }
        __syncthreads();
    }

    float cw = *cwp;
#pragma unroll
    for (int i = 0; i < 4; i++) {
        int m = bm + ty * 4 + i;
        float w0 = wts[m * 4 + 0], w1 = wts[m * 4 + 1], w2 = wts[m * 4 + 2];
        int   i0 = idxs[m * 4 + 0], i1 = idxs[m * 4 + 1], i2 = idxs[m * 4 + 2];
        const float* mv0 = MV + (size_t)i0 * HSZ;
        const float* mv1 = MV + (size_t)i1 * HSZ;
        const float* mv2 = MV + (size_t)i2 * HSZ;
        float out4[4];
#pragma unroll
        for (int j = 0; j < 4; j++) {
            int n = bn + tx * 4 + j;
            float v = cw * acc[i][j] + bout[n];
            v = fmaf(w0, mv0[n], v);
            v = fmaf(w1, mv1[n], v);
            v = fmaf(w2, mv2[n], v);
            out4[j] = v;
        }
        *(float4*)&C[(size_t)m * ldc + bn + tx * 4] =
            make_float4(out4[0], out4[1], out4[2], out4[3]);
    }
}

// =================================================================
// MV[m][h] = sum_h' mem_vals[m][h'] * W_out[h][256 + h']
// =================================================================
__global__ void mv_kernel(const float* __restrict__ vals,
                          const float* __restrict__ Wout,
                          float* __restrict__ mv)
{
    int m = blockIdx.x, h = threadIdx.x;
    const float* vrow = vals + (size_t)m * HSZ;
    const float* wrow = Wout + (size_t)h * 2 * HSZ + HSZ;
    float acc = 0.f;
#pragma unroll 8
    for (int k = 0; k < HSZ; k++) acc = fmaf(vrow[k], wrow[k], acc);
    mv[(size_t)m * HSZ + h] = acc;
}

// =================================================================
// LSTM scan (tensor-core, 5-term split-fp16): 2 clusters x 8 CTAs,
// 16 batches/cluster. h = h1 + 2^-11 h2' + 2^-22 h3',
// W = w1 + 2^-11 w2'. Three fp32 accumulator channels by scale:
//   A = w1h1;  B = w1h2' + w2'h1;  C = w1h3' + w2'h2'
//   gate = A + 2^-11 B + 2^-22 C      (product err ~2^-22, W-rep bound)
// via mma.sync.m16n8k16.f16. Weights stationary in regs; h exchanged
// through 3 L2-resident stage buffers in A-fragment layout (.cg),
// parity double-buffered, one barrier.cluster per step. Precise gates.
// =================================================================
__device__ __forceinline__ void cluster_sync_all() {
    asm volatile("barrier.cluster.arrive.aligned;" ::: "memory");
    asm volatile("barrier.cluster.wait.aligned;" ::: "memory");
}
__device__ __forceinline__ void mma_f16(float* d, const uint4& a,
                                        unsigned b0, unsigned b1) {
    asm volatile(
        "mma.sync.aligned.m16n8k16.row.col.f32.f16.f16.f32 "
        "{%0,%1,%2,%3},{%4,%5,%6,%7},{%8,%9},{%0,%1,%2,%3};"
        : "+f"(d[0]), "+f"(d[1]), "+f"(d[2]), "+f"(d[3])
        : "r"(a.x), "r"(a.y), "r"(a.z), "r"(a.w), "r"(b0), "r"(b1));
}
__device__ __forceinline__ void st16cg(void* p, unsigned short v) {
    asm volatile("st.global.cg.b16 [%0], %1;" :: "l"(p), "h"(v) : "memory");
}

__global__ __launch_bounds__(256, 1) __cluster_dims__(8, 1, 1)
void lstm_scan_mma(const float* __restrict__ xg,     // permuted [B][S][1024]
                   const __half* __restrict__ W1,    // perm [1024][256]
                   const __half* __restrict__ W2,    // scaled residual
                   float* __restrict__ hout)         // [B][S][256]
{
    int tid = threadIdx.x;
    int lane = tid & 31, w = tid >> 5;
    int crank = blockIdx.x & 7, cid = blockIdx.x >> 3;
    int lane4 = lane & 3, laneq = lane >> 2;

    // ---- stationary weight fragments: 2 ntiles x 16 ktiles x 2 regs ----
    unsigned w1r[2][16][2], w2r[2][16][2];
#pragma unroll
    for (int p = 0; p < 2; p++) {
        int n_g = crank * 128 + w * 16 + p * 8 + laneq;   // permuted gate row
        const unsigned* r1 = (const unsigned*)(W1 + (size_t)n_g * HSZ);
        const unsigned* r2 = (const unsigned*)(W2 + (size_t)n_g * HSZ);
#pragma unroll
        for (int kt = 0; kt < 16; kt++) {
            w1r[p][kt][0] = __ldg(r1 + kt * 8 + lane4);
            w1r[p][kt][1] = __ldg(r1 + kt * 8 + 4 + lane4);
            w2r[p][kt][0] = __ldg(r2 + kt * 8 + lane4);
            w2r[p][kt][1] = __ldg(r2 + kt * 8 + 4 + lane4);
        }
    }

    // ---- stage pointers + zero init (h_prev = 0) ----
    float* stg = g_hstage + (size_t)cid * 12288;  // [mat 3][par 2][2048]
    for (int i = crank * 1536 + tid; i < (crank + 1) * 1536; i += 256)
        __stcg(stg + i, 0.f);

    // ---- epilogue role: (batch, hcol) per ntile ----
    bool odd = (lane & 1) != 0;
    int b_loc = laneq + (odd ? 8 : 0);
    int b_glob = cid * 16 + b_loc;
    int hcl[2];
    hcl[0] = w * 4 + (lane4 >> 1);
    hcl[1] = hcl[0] + 2;
    const float* xgp[2];
    float* hop[2];
    unsigned soff[2];                       // fp16-granular stage offset
#pragma unroll
    for (int p = 0; p < 2; p++) {
        xgp[p] = xg + ((size_t)b_glob * SLEN) * G4 + crank * 128 + hcl[p] * 4;
        hop[p] = hout + ((size_t)b_glob * SLEN) * HSZ + crank * 32 + hcl[p];
        int k = crank * 32 + hcl[p];        // global k index of this h
        int kt = k >> 4, kin = k & 15, c = kin >> 1, half = kin & 1;
        int word = (c < 4 ? 0 : 2) + (b_loc < 8 ? 0 : 1);
        int lane_s = (b_loc & 7) * 4 + (c & 3);
        soff[p] = (unsigned)((((kt * 32 + lane_s) * 4 + word) * 2 + half));
    }
    float cst[2] = {0.f, 0.f};

    cluster_sync_all();   // stages zeroed cluster-wide

    const float S1 = 4.8828125e-4f;          // 2^-11

    for (int t = 0; t < SLEN; t++) {
        int par = t & 1;
        const uint4* s1 = (const uint4*)(stg + par * 2048);
        const uint4* s2 = (const uint4*)(stg + 4096 + par * 2048);
        const uint4* s3 = (const uint4*)(stg + 8192 + par * 2048);
        unsigned short* d1 = (unsigned short*)(stg + (par ^ 1) * 2048);
        unsigned short* d2 = (unsigned short*)(stg + 4096 + (par ^ 1) * 2048);
        unsigned short* d3 = (unsigned short*)(stg + 8192 + (par ^ 1) * 2048);

        // xg prefetch (consumed in epilogue; latency covered by MMAs)
        float4 xv0 = *(const float4*)(xgp[0] + (size_t)t * G4);
        float4 xv1 = *(const float4*)(xgp[1] + (size_t)t * G4);

        // A-fragment pipeline, depth 2 ktiles per matrix
        uint4 a1[2], a2[2], a3[2];
        a1[0] = __ldcg(s1 + lane);       a1[1] = __ldcg(s1 + 32 + lane);
        a2[0] = __ldcg(s2 + lane);       a2[1] = __ldcg(s2 + 32 + lane);
        a3[0] = __ldcg(s3 + lane);       a3[1] = __ldcg(s3 + 32 + lane);

        float A0[4] = {}, A1[4] = {}, B0[4] = {}, B1[4] = {};
        float C0[4] = {}, C1[4] = {};
#pragma unroll
        for (int kt = 0; kt < 16; kt++) {
            uint4 x1 = a1[kt & 1], x2 = a2[kt & 1], x3 = a3[kt & 1];
            if (kt + 2 < 16) {
                a1[kt & 1] = __ldcg(s1 + (kt + 2) * 32 + lane);
                a2[kt & 1] = __ldcg(s2 + (kt + 2) * 32 + lane);
                a3[kt & 1] = __ldcg(s3 + (kt + 2) * 32 + lane);
            }
            mma_f16(A0, x1, w1r[0][kt][0], w1r[0][kt][1]);
            mma_f16(A1, x1, w1r[1][kt][0], w1r[1][kt][1]);
            mma_f16(B0, x2, w1r[0][kt][0], w1r[0][kt][1]);
            mma_f16(B1, x2, w1r[1][kt][0], w1r[1][kt][1]);
            mma_f16(B0, x1, w2r[0][kt][0], w2r[0][kt][1]);
            mma_f16(B1, x1, w2r[1][kt][0], w2r[1][kt][1]);
            mma_f16(C0, x3, w1r[0][kt][0], w1r[0][kt][1]);
            mma_f16(C1, x3, w1r[1][kt][0], w1r[1][kt][1]);
            mma_f16(C0, x2, w2r[0][kt][0], w2r[0][kt][1]);
            mma_f16(C1, x2, w2r[1][kt][0], w2r[1][kt][1]);
        }

        // epilogue: combine scales, gather 4 gates via xor-1 shuffle
#pragma unroll
        for (int p = 0; p < 2; p++) {
            float* A = p ? A1 : A0;
            float* B = p ? B1 : B0;
            float* C = p ? C1 : C0;
            float g4[4];
#pragma unroll
            for (int i = 0; i < 4; i++)
                g4[i] = fmaf(S1, fmaf(S1, C[i], B[i]), A[i]);
            float e0 = __shfl_xor_sync(0xffffffffu, g4[0], 1);
            float e1 = __shfl_xor_sync(0xffffffffu, g4[1], 1);
            float e2 = __shfl_xor_sync(0xffffffffu, g4[2], 1);
            float e3 = __shfl_xor_sync(0xffffffffu, g4[3], 1);
            float gi, gf, gg, go;
            if (!odd) { gi = g4[0]; gf = g4[1]; gg = e0; go = e1; }
            else      { gi = e2;   gf = e3;   gg = g4[2]; go = g4[3]; }
            float4 xv = p ? xv1 : xv0;
            gi += xv.x; gf += xv.y; gg += xv.z; go += xv.w;
            float si = 1.f / (1.f + expf(-gi));
            float sf = 1.f / (1.f + expf(-gf));
            float so = 1.f / (1.f + expf(-go));
            float tg = tanhf(gg);
            cst[p] = fmaf(sf, cst[p], si * tg);
            float h = so * tanhf(cst[p]);
            hop[p][(size_t)t * HSZ] = h;
            // fp16 3-piece split with scaled residuals (all normal-range)
            __half h1 = __float2half_rn(h);
            float r = h - __half2float(h1);
            __half h2 = __float2half_rn(r * 2048.f);
            float r2 = r - __half2float(h2) * S1;
            __half h3 = __float2half_rn(r2 * 4194304.f);   // * 2^22
            st16cg(d1 + soff[p], __half_as_ushort(h1));
            st16cg(d2 + soff[p], __half_as_ushort(h2));
            st16cg(d3 + soff[p], __half_as_ushort(h3));
        }
        cluster_sync_all();   // release h stores / acquire peers' stage
    }
}

// =================================================================
// kNN over quantum memory: per token -> 3 indices + 3 scaled weights
// =================================================================
__global__ __launch_bounds__(256) void knn_kernel(
    const float* __restrict__ lstm,
    const float* __restrict__ Wcq, const float* __restrict__ bcq,
    const float* __restrict__ keys, const float* __restrict__ qwp,
    float* __restrict__ wout, int* __restrict__ idxout)
{
    __shared__ float sWcq[QDIM][HSZ];
    __shared__ float skn[MMEM][QDIM];
    __shared__ __align__(16) float sh[8][HSZ];
    __shared__ float sq[8][QDIM];
    __shared__ float ssims[8][MMEM];
    int tid = threadIdx.x;
    for (int i = tid; i < QDIM * HSZ; i += 256)
        sWcq[i >> 8][i & 255] = Wcq[i];
    if (tid < MMEM) {
        float kv[QDIM]; float nrm = 0.f;
#pragma unroll
        for (int d = 0; d < QDIM; d++) { kv[d] = keys[tid * QDIM + d]; nrm += kv[d] * kv[d]; }
        float inv = 1.f / (sqrtf(nrm) + 1e-8f);
#pragma unroll
        for (int d = 0; d < QDIM; d++) skn[tid][d] = kv[d] * inv;
    }
    __syncthreads();

    int wid = tid >> 5, lane = tid & 31;
    int token = blockIdx.x * 8 + wid;
    const float* hrow = lstm + (size_t)token * HSZ;
    for (int i = lane; i < HSZ / 4; i += 32)
        ((float4*)sh[wid])[i] = ((const float4*)hrow)[i];
    __syncwarp();
    if (lane < QDIM) {
        float acc = bcq[lane];
#pragma unroll 8
        for (int k = 0; k < HSZ; k++) acc = fmaf(sWcq[lane][k], sh[wid][k], acc);
        sq[wid][lane] = tanhf(acc);
    }
    __syncwarp();
    float qn[QDIM];
    {
        float nrm = 0.f;
#pragma unroll
        for (int d = 0; d < QDIM; d++) { float v = sq[wid][d]; nrm += v * v; }
        float inv = 1.f / (sqrtf(nrm) + 1e-8f);
#pragma unroll
        for (int d = 0; d < QDIM; d++) qn[d] = sq[wid][d] * inv;
    }
#pragma unroll
    for (int mm = 0; mm < 2; mm++) {
        int m = lane + mm * 32;
        float s = 0.f;
#pragma unroll
        for (int d = 0; d < QDIM; d++) s = fmaf(qn[d], skn[m][d], s);
        ssims[wid][m] = s;
    }
    __syncwarp();
    if (lane == 0) {
        float v0 = -1e30f, v1 = -1e30f, v2 = -1e30f;
        int i0 = 0, i1 = 0, i2 = 0;
        for (int m = 0; m < MMEM; m++) {
            float s = ssims[wid][m];
            if (s > v0)      { v2 = v1; i2 = i1; v1 = v0; i1 = i0; v0 = s; i0 = m; }
            else if (s > v1) { v2 = v1; i2 = i1; v1 = s;  i1 = m; }
            else if (s > v2) { v2 = s;  i2 = m; }
        }
        float tot = v0 + v1 + v2;
        float qw = *qwp;
        float sc = (tot > 0.f) ? (qw / tot) : 0.f;
        wout[token * 4 + 0] = v0 * sc;
        wout[token * 4 + 1] = v1 * sc;
        wout[token * 4 + 2] = v2 * sc;
        idxout[token * 4 + 0] = i0;
        idxout[token * 4 + 1] = i1;
        idxout[token * 4 + 2] = i2;
    }
}

// =================================================================
extern "C" void kernel_launch(void* const* d_in, const int* in_sizes, int n_in,
                              void* d_out, int out_size) {
    const float* x      = (const float*)d_in[0];
    const float* W_ih0  = (const float*)d_in[1];
    const float* W_hh0  = (const float*)d_in[2];
    const float* b_ih0  = (const float*)d_in[3];
    const float* b_hh0  = (const float*)d_in[4];
    const float* W_ih1  = (const float*)d_in[5];
    const float* W_hh1  = (const float*)d_in[6];
    const float* b_ih1  = (const float*)d_in[7];
    const float* b_hh1  = (const float*)d_in[8];
    const float* W_cq   = (const float*)d_in[9];
    const float* b_cq   = (const float*)d_in[10];
    const float* mkeys  = (const float*)d_in[11];
    const float* mvals  = (const float*)d_in[12];
    const float* W_out  = (const float*)d_in[13];
    const float* b_out  = (const float*)d_in[14];
    const float* cw     = (const float*)d_in[15];
    const float* qw     = (const float*)d_in[16];
    float* out = (float*)d_out;

    float* xg   = nullptr; cudaGetSymbolAddress((void**)&xg,   g_xg);
    float* hbf  = nullptr; cudaGetSymbolAddress((void**)&hbf,  g_h);
    float* mv   = nullptr; cudaGetSymbolAddress((void**)&mv,   g_mv);
    float* wts  = nullptr; cudaGetSymbolAddress((void**)&wts,  g_w);
    int*   idx  = nullptr; cudaGetSymbolAddress((void**)&idx,  g_idx);
    __half* W10 = nullptr; cudaGetSymbolAddress((void**)&W10, g_W1_0);
    __half* W20 = nullptr; cudaGetSymbolAddress((void**)&W20, g_W2_0);
    __half* W11 = nullptr; cudaGetSymbolAddress((void**)&W11, g_W1_1);
    __half* W21 = nullptr; cudaGetSymbolAddress((void**)&W21, g_W2_1);
    float* Wpi0 = nullptr; cudaGetSymbolAddress((void**)&Wpi0, g_Wp_ih0);
    float* Wpi1 = nullptr; cudaGetSymbolAddress((void**)&Wpi1, g_Wp_ih1);
    float* bp0  = nullptr; cudaGetSymbolAddress((void**)&bp0,  g_bp0);
    float* bp1  = nullptr; cudaGetSymbolAddress((void**)&bp1,  g_bp1);

    // #1 permute weights/biases + fp16 split of W_hh
    prep_kernel<<<G4, 256>>>(W_hh0, W_hh1, W_ih0, W_ih1,
                             b_ih0, b_hh0, b_ih1, b_hh1);
    // #2
    mv_kernel<<<MMEM, HSZ>>>(mvals, W_out, mv);

    // #3 xg0 = x @ Wp_ih0^T + bias (permuted layout)
    {
        dim3 grid(G4 / 64, NTOK / 64);
        gemm_bt_kernel<<<grid, 256>>>(x, NIN, Wpi0, NIN, xg, G4, NIN, bp0);
    }
    // #4 scan layer 0
    lstm_scan_mma<<<16, 256>>>(xg, W10, W20, hbf);

    // #5 xg1 = h1 @ Wp_ih1^T + bias
    {
        dim3 grid(G4 / 64, NTOK / 64);
        gemm_bt_kernel<<<grid, 256>>>(hbf, HSZ, Wpi1, HSZ, xg, G4, HSZ, bp1);
    }
    // #6 scan layer 1  (ncu -s 5 -c 1 capture slot)
    lstm_scan_mma<<<16, 256>>>(xg, W11, W21, hbf);

    // #7 kNN metadata
    knn_kernel<<<NTOK / 8, 256>>>(hbf, W_cq, b_cq, mkeys, qw, wts, idx);

    // #8 out = cw*(lstm@Wc^T) + b_out + sum_k w_k*MV[idx_k]
    {
        dim3 grid(HSZ / 64, NTOK / 64);
        out_gemm_kernel<<<grid, 256>>>(hbf, HSZ, W_out, 2 * HSZ, out, HSZ, HSZ,
                                       b_out, cw, wts, idx, mv);
    }
}

// round 9
// speedup vs baseline: 2.4662x; 1.0198x over previous
#include <cuda_runtime.h>
#include <cuda_bf16.h>
#include <cuda_fp16.h>
#include <math.h>
#include <stdint.h>

#define NBATCH 32
#define SLEN   2048
#define NIN    128
#define HSZ    256
#define G4     1024
#define NTOK   (NBATCH * SLEN)   // 65536
#define QDIM   16
#define MMEM   64

// ---------------- static scratch (allocation-free) ----------------
__device__ float g_xg[(size_t)NTOK * G4];   // permuted xg for current layer
__device__ float g_h [(size_t)NTOK * HSZ];  // h1, then lstm_out
__device__ float g_mv[MMEM * HSZ];          // mem_vals @ Wq^T
__device__ float g_w [NTOK * 4];            // per-token scaled top3 weights
__device__ int   g_idx[NTOK * 4];           // per-token top3 indices
// permuted W_hh split: w1 = fp16(w), w2s = fp16((w - w1) * 2^11)
__device__ __half g_W1_0[G4 * HSZ];
__device__ __half g_W2_0[G4 * HSZ];
__device__ __half g_W1_1[G4 * HSZ];
__device__ __half g_W2_1[G4 * HSZ];
__device__ float g_Wp_ih0[G4 * NIN];
__device__ float g_Wp_ih1[G4 * HSZ];
__device__ float g_bp0[G4];
__device__ float g_bp1[G4];
// h stage: per cluster 2 matrices (h1,h2') x 2 parity x 2048 u32 words
__device__ float g_hstage[2 * 2 * 2 * 2048];

// =================================================================
// Weight/bias permutation + fp16 hi/scaled-lo split for W_hh
// =================================================================
__global__ void prep_kernel(const float* __restrict__ Whh0,
                            const float* __restrict__ Whh1,
                            const float* __restrict__ Wih0,
                            const float* __restrict__ Wih1,
                            const float* __restrict__ bih0,
                            const float* __restrict__ bhh0,
                            const float* __restrict__ bih1,
                            const float* __restrict__ bhh1)
{
    int p = blockIdx.x;                   // permuted row 0..1023
    int src = (p & 3) * HSZ + (p >> 2);   // gate = p&3, hcol = p>>2
    int tid = threadIdx.x;
    for (int k = tid; k < HSZ; k += blockDim.x) {
        float v0 = Whh0[src * HSZ + k];
        __half a0 = __float2half_rn(v0);
        g_W1_0[p * HSZ + k] = a0;
        g_W2_0[p * HSZ + k] = __float2half_rn((v0 - __half2float(a0)) * 2048.f);
        float v1 = Whh1[src * HSZ + k];
        __half a1 = __float2half_rn(v1);
        g_W1_1[p * HSZ + k] = a1;
        g_W2_1[p * HSZ + k] = __float2half_rn((v1 - __half2float(a1)) * 2048.f);
        g_Wp_ih1[p * HSZ + k] = Wih1[src * HSZ + k];
    }
    for (int k = tid; k < NIN; k += blockDim.x)
        g_Wp_ih0[p * NIN + k] = Wih0[src * NIN + k];
    if (tid == 0) {
        g_bp0[p] = bih0[src] + bhh0[src];
        g_bp1[p] = bih1[src] + bhh1[src];
    }
}

// =================================================================
// Tiled SIMT GEMM: C[m,n] = sum_k A[m,k]*B[n,k] + bias[n]
// =================================================================
__global__ __launch_bounds__(256) void gemm_bt_kernel(
    const float* __restrict__ A, int lda,
    const float* __restrict__ B, int ldb,
    float* __restrict__ C, int ldc,
    int K,
    const float* __restrict__ bias1)
{
    __shared__ __align__(16) float As[16][68];
    __shared__ __align__(16) float Bs[16][68];
    int tid = threadIdx.x;
    int bm = blockIdx.y * 64, bn = blockIdx.x * 64;
    int lr = tid >> 2, lk = (tid & 3) * 4;
    int tx = tid & 15, ty = tid >> 4;
    float acc[4][4] = {};
    const float* Ap = A + (size_t)(bm + lr) * lda + lk;
    const float* Bp = B + (size_t)(bn + lr) * ldb + lk;

    for (int k0 = 0; k0 < K; k0 += 16) {
        float4 av = *(const float4*)(Ap + k0);
        float4 bv = *(const float4*)(Bp + k0);
        As[lk + 0][lr] = av.x; As[lk + 1][lr] = av.y;
        As[lk + 2][lr] = av.z; As[lk + 3][lr] = av.w;
        Bs[lk + 0][lr] = bv.x; Bs[lk + 1][lr] = bv.y;
        Bs[lk + 2][lr] = bv.z; Bs[lk + 3][lr] = bv.w;
        __syncthreads();
#pragma unroll
        for (int kk = 0; kk < 16; kk++) {
            float4 a4 = *(const float4*)&As[kk][ty * 4];
            float4 b4 = *(const float4*)&Bs[kk][tx * 4];
            float a[4] = {a4.x, a4.y, a4.z, a4.w};
            float b[4] = {b4.x, b4.y, b4.z, b4.w};
#pragma unroll
            for (int i = 0; i < 4; i++)
#pragma unroll
                for (int j = 0; j < 4; j++)
                    acc[i][j] = fmaf(a[i], b[j], acc[i][j]);
        }
        __syncthreads();
    }

    float bcol[4];
#pragma unroll
    for (int j = 0; j < 4; j++)
        bcol[j] = bias1 ? bias1[bn + tx * 4 + j] : 0.f;
#pragma unroll
    for (int i = 0; i < 4; i++) {
        int m = bm + ty * 4 + i;
        float4 o;
        o.x = acc[i][0] + bcol[0];
        o.y = acc[i][1] + bcol[1];
        o.z = acc[i][2] + bcol[2];
        o.w = acc[i][3] + bcol[3];
        *(float4*)&C[(size_t)m * ldc + bn + tx * 4] = o;
    }
}

// =================================================================
// Output GEMM with fused quantum-memory epilogue
// =================================================================
__global__ __launch_bounds__(256) void out_gemm_kernel(
    const float* __restrict__ A, int lda,
    const float* __restrict__ B, int ldb,
    float* __restrict__ C, int ldc,
    int K,
    const float* __restrict__ bout,
    const float* __restrict__ cwp,
    const float* __restrict__ wts,
    const int*   __restrict__ idxs,
    const float* __restrict__ MV)
{
    __shared__ __align__(16) float As[16][68];
    __shared__ __align__(16) float Bs[16][68];
    int tid = threadIdx.x;
    int bm = blockIdx.y * 64, bn = blockIdx.x * 64;
    int lr = tid >> 2, lk = (tid & 3) * 4;
    int tx = tid & 15, ty = tid >> 4;
    float acc[4][4] = {};
    const float* Ap = A + (size_t)(bm + lr) * lda + lk;
    const float* Bp = B + (size_t)(bn + lr) * ldb + lk;

    for (int k0 = 0; k0 < K; k0 += 16) {
        float4 av = *(const float4*)(Ap + k0);
        float4 bv = *(const float4*)(Bp + k0);
        As[lk + 0][lr] = av.x; As[lk + 1][lr] = av.y;
        As[lk + 2][lr] = av.z; As[lk + 3][lr] = av.w;
        Bs[lk + 0][lr] = bv.x; Bs[lk + 1][lr] = bv.y;
        Bs[lk + 2][lr] = bv.z; Bs[lk + 3][lr] = bv.w;
        __syncthreads();
#pragma unroll
        for (int kk = 0; kk < 16; kk++) {
            float4 a4 = *(const float4*)&As[kk][ty * 4];
            float4 b4 = *(const float4*)&Bs[kk][tx * 4];
            float a[4] = {a4.x, a4.y, a4.z, a4.w};
            float b[4] = {b4.x, b4.y, b4.z, b4.w};
#pragma unroll
            for (int i = 0; i < 4; i++)
#pragma unroll
                for (int j = 0; j < 4; j++)
                    acc[i][j] = fmaf(a[i], b[j], acc[i][j]);
        }
        __syncthreads();
    }

    float cw = *cwp;
#pragma unroll
    for (int i = 0; i < 4; i++) {
        int m = bm + ty * 4 + i;
        float w0 = wts[m * 4 + 0], w1 = wts[m * 4 + 1], w2 = wts[m * 4 + 2];
        int   i0 = idxs[m * 4 + 0], i1 = idxs[m * 4 + 1], i2 = idxs[m * 4 + 2];
        const float* mv0 = MV + (size_t)i0 * HSZ;
        const float* mv1 = MV + (size_t)i1 * HSZ;
        const float* mv2 = MV + (size_t)i2 * HSZ;
        float out4[4];
#pragma unroll
        for (int j = 0; j < 4; j++) {
            int n = bn + tx * 4 + j;
            float v = cw * acc[i][j] + bout[n];
            v = fmaf(w0, mv0[n], v);
            v = fmaf(w1, mv1[n], v);
            v = fmaf(w2, mv2[n], v);
            out4[j] = v;
        }
        *(float4*)&C[(size_t)m * ldc + bn + tx * 4] =
            make_float4(out4[0], out4[1], out4[2], out4[3]);
    }
}

// =================================================================
// MV[m][h] = sum_h' mem_vals[m][h'] * W_out[h][256 + h']
// =================================================================
__global__ void mv_kernel(const float* __restrict__ vals,
                          const float* __restrict__ Wout,
                          float* __restrict__ mv)
{
    int m = blockIdx.x, h = threadIdx.x;
    const float* vrow = vals + (size_t)m * HSZ;
    const float* wrow = Wout + (size_t)h * 2 * HSZ + HSZ;
    float acc = 0.f;
#pragma unroll 8
    for (int k = 0; k < HSZ; k++) acc = fmaf(vrow[k], wrow[k], acc);
    mv[(size_t)m * HSZ + h] = acc;
}

// =================================================================
// LSTM scan (tensor-core, exact 2x2-piece fp16): 2 clusters x 8 CTAs,
// 16 batches/cluster. h = h1 + 2^-11 h2', W = w1 + 2^-11 w2'.
// Full expansion in three fp32 channels by scale (NO dropped terms):
//   A = w1h1;  B = w1h2' + w2'h1;  C = w2'h2'
//   gate = A + 2^-11 (B + 2^-11 C)     (rep err ~2^-24 per element)
// 8 MMA/ktile via mma.sync.m16n8k16.f16. Weights stationary in regs;
// h exchanged through 2 L2-resident stage buffers in A-fragment
// layout (.cg), parity double-buffered, depth-4 load pipeline, one
// barrier.cluster per step. Precise gates.
// =================================================================
__device__ __forceinline__ void cluster_sync_all() {
    asm volatile("barrier.cluster.arrive.aligned;" ::: "memory");
    asm volatile("barrier.cluster.wait.aligned;" ::: "memory");
}
__device__ __forceinline__ void mma_f16(float* d, const uint4& a,
                                        unsigned b0, unsigned b1) {
    asm volatile(
        "mma.sync.aligned.m16n8k16.row.col.f32.f16.f16.f32 "
        "{%0,%1,%2,%3},{%4,%5,%6,%7},{%8,%9},{%0,%1,%2,%3};"
        : "+f"(d[0]), "+f"(d[1]), "+f"(d[2]), "+f"(d[3])
        : "r"(a.x), "r"(a.y), "r"(a.z), "r"(a.w), "r"(b0), "r"(b1));
}
__device__ __forceinline__ void st16cg(void* p, unsigned short v) {
    asm volatile("st.global.cg.b16 [%0], %1;" :: "l"(p), "h"(v) : "memory");
}

__global__ __launch_bounds__(256, 1) __cluster_dims__(8, 1, 1)
void lstm_scan_mma(const float* __restrict__ xg,     // permuted [B][S][1024]
                   const __half* __restrict__ W1,    // perm [1024][256]
                   const __half* __restrict__ W2,    // scaled residual
                   float* __restrict__ hout)         // [B][S][256]
{
    int tid = threadIdx.x;
    int lane = tid & 31, w = tid >> 5;
    int crank = blockIdx.x & 7, cid = blockIdx.x >> 3;
    int lane4 = lane & 3, laneq = lane >> 2;

    // ---- stationary weight fragments: 2 ntiles x 16 ktiles x 2 regs ----
    unsigned w1r[2][16][2], w2r[2][16][2];
#pragma unroll
    for (int p = 0; p < 2; p++) {
        int n_g = crank * 128 + w * 16 + p * 8 + laneq;   // permuted gate row
        const unsigned* r1 = (const unsigned*)(W1 + (size_t)n_g * HSZ);
        const unsigned* r2 = (const unsigned*)(W2 + (size_t)n_g * HSZ);
#pragma unroll
        for (int kt = 0; kt < 16; kt++) {
            w1r[p][kt][0] = __ldg(r1 + kt * 8 + lane4);
            w1r[p][kt][1] = __ldg(r1 + kt * 8 + 4 + lane4);
            w2r[p][kt][0] = __ldg(r2 + kt * 8 + lane4);
            w2r[p][kt][1] = __ldg(r2 + kt * 8 + 4 + lane4);
        }
    }

    // ---- stage pointers + zero init (h_prev = 0) ----
    float* stg = g_hstage + (size_t)cid * 8192;  // [mat 2][par 2][2048]
    for (int i = crank * 1024 + tid; i < (crank + 1) * 1024; i += 256)
        __stcg(stg + i, 0.f);

    // ---- epilogue role: (batch, hcol) per ntile ----
    bool odd = (lane & 1) != 0;
    int b_loc = laneq + (odd ? 8 : 0);
    int b_glob = cid * 16 + b_loc;
    int hcl[2];
    hcl[0] = w * 4 + (lane4 >> 1);
    hcl[1] = hcl[0] + 2;
    const float* xgp[2];
    float* hop[2];
    unsigned soff[2];                       // fp16-granular stage offset
#pragma unroll
    for (int p = 0; p < 2; p++) {
        xgp[p] = xg + ((size_t)b_glob * SLEN) * G4 + crank * 128 + hcl[p] * 4;
        hop[p] = hout + ((size_t)b_glob * SLEN) * HSZ + crank * 32 + hcl[p];
        int k = crank * 32 + hcl[p];        // global k index of this h
        int kt = k >> 4, kin = k & 15, c = kin >> 1, half = kin & 1;
        int word = (c < 4 ? 0 : 2) + (b_loc < 8 ? 0 : 1);
        int lane_s = (b_loc & 7) * 4 + (c & 3);
        soff[p] = (unsigned)((((kt * 32 + lane_s) * 4 + word) * 2 + half));
    }
    float cst[2] = {0.f, 0.f};

    cluster_sync_all();   // stages zeroed cluster-wide

    const float S1 = 4.8828125e-4f;          // 2^-11

    for (int t = 0; t < SLEN; t++) {
        int par = t & 1;
        const uint4* s1 = (const uint4*)(stg + par * 2048);
        const uint4* s2 = (const uint4*)(stg + 4096 + par * 2048);
        unsigned short* d1 = (unsigned short*)(stg + (par ^ 1) * 2048);
        unsigned short* d2 = (unsigned short*)(stg + 4096 + (par ^ 1) * 2048);

        // xg prefetch (consumed in epilogue; latency covered by MMAs)
        float4 xv0 = *(const float4*)(xgp[0] + (size_t)t * G4);
        float4 xv1 = *(const float4*)(xgp[1] + (size_t)t * G4);

        // A-fragment pipeline, depth 4 ktiles per matrix
        uint4 a1[4], a2[4];
#pragma unroll
        for (int i = 0; i < 4; i++) {
            a1[i] = __ldcg(s1 + i * 32 + lane);
            a2[i] = __ldcg(s2 + i * 32 + lane);
        }

        float A0[4] = {}, A1v[4] = {}, B0[4] = {}, B1v[4] = {};
        float C0[4] = {}, C1v[4] = {};
#pragma unroll
        for (int kt = 0; kt < 16; kt++) {
            uint4 x1 = a1[kt & 3], x2 = a2[kt & 3];
            if (kt + 4 < 16) {
                a1[kt & 3] = __ldcg(s1 + (kt + 4) * 32 + lane);
                a2[kt & 3] = __ldcg(s2 + (kt + 4) * 32 + lane);
            }
            mma_f16(A0,  x1, w1r[0][kt][0], w1r[0][kt][1]);
            mma_f16(A1v, x1, w1r[1][kt][0], w1r[1][kt][1]);
            mma_f16(B0,  x2, w1r[0][kt][0], w1r[0][kt][1]);
            mma_f16(B1v, x2, w1r[1][kt][0], w1r[1][kt][1]);
            mma_f16(B0,  x1, w2r[0][kt][0], w2r[0][kt][1]);
            mma_f16(B1v, x1, w2r[1][kt][0], w2r[1][kt][1]);
            mma_f16(C0,  x2, w2r[0][kt][0], w2r[0][kt][1]);
            mma_f16(C1v, x2, w2r[1][kt][0], w2r[1][kt][1]);
        }

        // epilogue: combine scales, gather 4 gates via xor-1 shuffle
#pragma unroll
        for (int p = 0; p < 2; p++) {
            float* A = p ? A1v : A0;
            float* B = p ? B1v : B0;
            float* C = p ? C1v : C0;
            float g4[4];
#pragma unroll
            for (int i = 0; i < 4; i++)
                g4[i] = fmaf(S1, fmaf(S1, C[i], B[i]), A[i]);
            float e0 = __shfl_xor_sync(0xffffffffu, g4[0], 1);
            float e1 = __shfl_xor_sync(0xffffffffu, g4[1], 1);
            float e2 = __shfl_xor_sync(0xffffffffu, g4[2], 1);
            float e3 = __shfl_xor_sync(0xffffffffu, g4[3], 1);
            float gi, gf, gg, go;
            if (!odd) { gi = g4[0]; gf = g4[1]; gg = e0; go = e1; }
            else      { gi = e2;   gf = e3;   gg = g4[2]; go = g4[3]; }
            float4 xv = p ? xv1 : xv0;
            gi += xv.x; gf += xv.y; gg += xv.z; go += xv.w;
            float si = 1.f / (1.f + expf(-gi));
            float sf = 1.f / (1.f + expf(-gf));
            float so = 1.f / (1.f + expf(-go));
            float tg = tanhf(gg);
            cst[p] = fmaf(sf, cst[p], si * tg);
            float h = so * tanhf(cst[p]);
            hop[p][(size_t)t * HSZ] = h;
            // fp16 2-piece split with scaled residual
            __half h1 = __float2half_rn(h);
            float r = (h - __half2float(h1)) * 2048.f;
            __half h2 = __float2half_rn(r);
            st16cg(d1 + soff[p], __half_as_ushort(h1));
            st16cg(d2 + soff[p], __half_as_ushort(h2));
        }
        cluster_sync_all();   // release h stores / acquire peers' stage
    }
}

// =================================================================
// kNN over quantum memory: per token -> 3 indices + 3 scaled weights
// =================================================================
__global__ __launch_bounds__(256) void knn_kernel(
    const float* __restrict__ lstm,
    const float* __restrict__ Wcq, const float* __restrict__ bcq,
    const float* __restrict__ keys, const float* __restrict__ qwp,
    float* __restrict__ wout, int* __restrict__ idxout)
{
    __shared__ float sWcq[QDIM][HSZ];
    __shared__ float skn[MMEM][QDIM];
    __shared__ __align__(16) float sh[8][HSZ];
    __shared__ float sq[8][QDIM];
    __shared__ float ssims[8][MMEM];
    int tid = threadIdx.x;
    for (int i = tid; i < QDIM * HSZ; i += 256)
        sWcq[i >> 8][i & 255] = Wcq[i];
    if (tid < MMEM) {
        float kv[QDIM]; float nrm = 0.f;
#pragma unroll
        for (int d = 0; d < QDIM; d++) { kv[d] = keys[tid * QDIM + d]; nrm += kv[d] * kv[d]; }
        float inv = 1.f / (sqrtf(nrm) + 1e-8f);
#pragma unroll
        for (int d = 0; d < QDIM; d++) skn[tid][d] = kv[d] * inv;
    }
    __syncthreads();

    int wid = tid >> 5, lane = tid & 31;
    int token = blockIdx.x * 8 + wid;
    const float* hrow = lstm + (size_t)token * HSZ;
    for (int i = lane; i < HSZ / 4; i += 32)
        ((float4*)sh[wid])[i] = ((const float4*)hrow)[i];
    __syncwarp();
    if (lane < QDIM) {
        float acc = bcq[lane];
#pragma unroll 8
        for (int k = 0; k < HSZ; k++) acc = fmaf(sWcq[lane][k], sh[wid][k], acc);
        sq[wid][lane] = tanhf(acc);
    }
    __syncwarp();
    float qn[QDIM];
    {
        float nrm = 0.f;
#pragma unroll
        for (int d = 0; d < QDIM; d++) { float v = sq[wid][d]; nrm += v * v; }
        float inv = 1.f / (sqrtf(nrm) + 1e-8f);
#pragma unroll
        for (int d = 0; d < QDIM; d++) qn[d] = sq[wid][d] * inv;
    }
#pragma unroll
    for (int mm = 0; mm < 2; mm++) {
        int m = lane + mm * 32;
        float s = 0.f;
#pragma unroll
        for (int d = 0; d < QDIM; d++) s = fmaf(qn[d], skn[m][d], s);
        ssims[wid][m] = s;
    }
    __syncwarp();
    if (lane == 0) {
        float v0 = -1e30f, v1 = -1e30f, v2 = -1e30f;
        int i0 = 0, i1 = 0, i2 = 0;
        for (int m = 0; m < MMEM; m++) {
            float s = ssims[wid][m];
            if (s > v0)      { v2 = v1; i2 = i1; v1 = v0; i1 = i0; v0 = s; i0 = m; }
            else if (s > v1) { v2 = v1; i2 = i1; v1 = s;  i1 = m; }
            else if (s > v2) { v2 = s;  i2 = m; }
        }
        float tot = v0 + v1 + v2;
        float qw = *qwp;
        float sc = (tot > 0.f) ? (qw / tot) : 0.f;
        wout[token * 4 + 0] = v0 * sc;
        wout[token * 4 + 1] = v1 * sc;
        wout[token * 4 + 2] = v2 * sc;
        idxout[token * 4 + 0] = i0;
        idxout[token * 4 + 1] = i1;
        idxout[token * 4 + 2] = i2;
    }
}

// =================================================================
extern "C" void kernel_launch(void* const* d_in, const int* in_sizes, int n_in,
                              void* d_out, int out_size) {
    const float* x      = (const float*)d_in[0];
    const float* W_ih0  = (const float*)d_in[1];
    const float* W_hh0  = (const float*)d_in[2];
    const float* b_ih0  = (const float*)d_in[3];
    const float* b_hh0  = (const float*)d_in[4];
    const float* W_ih1  = (const float*)d_in[5];
    const float* W_hh1  = (const float*)d_in[6];
    const float* b_ih1  = (const float*)d_in[7];
    const float* b_hh1  = (const float*)d_in[8];
    const float* W_cq   = (const float*)d_in[9];
    const float* b_cq   = (const float*)d_in[10];
    const float* mkeys  = (const float*)d_in[11];
    const float* mvals  = (const float*)d_in[12];
    const float* W_out  = (const float*)d_in[13];
    const float* b_out  = (const float*)d_in[14];
    const float* cw     = (const float*)d_in[15];
    const float* qw     = (const float*)d_in[16];
    float* out = (float*)d_out;

    float* xg   = nullptr; cudaGetSymbolAddress((void**)&xg,   g_xg);
    float* hbf  = nullptr; cudaGetSymbolAddress((void**)&hbf,  g_h);
    float* mv   = nullptr; cudaGetSymbolAddress((void**)&mv,   g_mv);
    float* wts  = nullptr; cudaGetSymbolAddress((void**)&wts,  g_w);
    int*   idx  = nullptr; cudaGetSymbolAddress((void**)&idx,  g_idx);
    __half* W10 = nullptr; cudaGetSymbolAddress((void**)&W10, g_W1_0);
    __half* W20 = nullptr; cudaGetSymbolAddress((void**)&W20, g_W2_0);
    __half* W11 = nullptr; cudaGetSymbolAddress((void**)&W11, g_W1_1);
    __half* W21 = nullptr; cudaGetSymbolAddress((void**)&W21, g_W2_1);
    float* Wpi0 = nullptr; cudaGetSymbolAddress((void**)&Wpi0, g_Wp_ih0);
    float* Wpi1 = nullptr; cudaGetSymbolAddress((void**)&Wpi1, g_Wp_ih1);
    float* bp0  = nullptr; cudaGetSymbolAddress((void**)&bp0,  g_bp0);
    float* bp1  = nullptr; cudaGetSymbolAddress((void**)&bp1,  g_bp1);

    // #1 permute weights/biases + fp16 split of W_hh
    prep_kernel<<<G4, 256>>>(W_hh0, W_hh1, W_ih0, W_ih1,
                             b_ih0, b_hh0, b_ih1, b_hh1);
    // #2
    mv_kernel<<<MMEM, HSZ>>>(mvals, W_out, mv);

    // #3 xg0 = x @ Wp_ih0^T + bias (permuted layout)
    {
        dim3 grid(G4 / 64, NTOK / 64);
        gemm_bt_kernel<<<grid, 256>>>(x, NIN, Wpi0, NIN, xg, G4, NIN, bp0);
    }
    // #4 scan layer 0
    lstm_scan_mma<<<16, 256>>>(xg, W10, W20, hbf);

    // #5 xg1 = h1 @ Wp_ih1^T + bias
    {
        dim3 grid(G4 / 64, NTOK / 64);
        gemm_bt_kernel<<<grid, 256>>>(hbf, HSZ, Wpi1, HSZ, xg, G4, HSZ, bp1);
    }
    // #6 scan layer 1  (ncu -s 5 -c 1 capture slot)
    lstm_scan_mma<<<16, 256>>>(xg, W11, W21, hbf);

    // #7 kNN metadata
    knn_kernel<<<NTOK / 8, 256>>>(hbf, W_cq, b_cq, mkeys, qw, wts, idx);

    // #8 out = cw*(lstm@Wc^T) + b_out + sum_k w_k*MV[idx_k]
    {
        dim3 grid(HSZ / 64, NTOK / 64);
        out_gemm_kernel<<<grid, 256>>>(hbf, HSZ, W_out, 2 * HSZ, out, HSZ, HSZ,
                                       b_out, cw, wts, idx, mv);
    }
}

// round 11
// speedup vs baseline: 4.8485x; 1.9660x over previous
#include <cuda_runtime.h>
#include <cuda_bf16.h>
#include <cuda_fp16.h>
#include <math.h>
#include <stdint.h>

#define NBATCH 32
#define SLEN   2048
#define NIN    128
#define HSZ    256
#define G4     1024
#define NTOK   (NBATCH * SLEN)   // 65536
#define QDIM   16
#define MMEM   64
#define NCHUNK 128               // 2048 steps / 16 per chunk
#define NTILES 128               // xg1 tiles per chunk (8 M x 16 N)
#define NWORK  64                // worker CTAs (8 clusters)

// ---------------- static scratch (allocation-free) ----------------
__device__ float g_xg0[(size_t)NTOK * G4];  // permuted xg, layer 0
__device__ float g_xg1[(size_t)NTOK * G4];  // permuted xg, layer 1
__device__ float g_h  [(size_t)NTOK * HSZ]; // h1 (layer-0 output)
__device__ float g_h2 [(size_t)NTOK * HSZ]; // lstm_out (layer-1 output)
__device__ float g_mv[MMEM * HSZ];          // mem_vals @ Wq^T
__device__ float g_w [NTOK * 4];            // per-token scaled top3 weights
__device__ int   g_idx[NTOK * 4];           // per-token top3 indices
// permuted W_hh split: w1 = fp16(w), w2s = fp16((w - w1) * 2^11)
__device__ __half g_W1_0[G4 * HSZ];
__device__ __half g_W2_0[G4 * HSZ];
__device__ __half g_W1_1[G4 * HSZ];
__device__ __half g_W2_1[G4 * HSZ];
__device__ float g_Wp_ih0[G4 * NIN];
__device__ float g_Wp_ih1[G4 * HSZ];
__device__ float g_bp0[G4];
__device__ float g_bp1[G4];
// h stage: [role 2][cid 2][mat 2][parity 2][2048 u32 words]
__device__ float g_hstage[4 * 8192];
// pipeline sync
__device__ int g_cnt_xg1[NCHUNK];
__device__ int g_wm_h1[16];

// =================================================================
// sync helpers
// =================================================================
__device__ __forceinline__ int ld_acq(const int* p) {
    int v;
    asm volatile("ld.acquire.gpu.u32 %0, [%1];" : "=r"(v) : "l"(p) : "memory");
    return v;
}
__device__ __forceinline__ void st_rel(int* p, int v) {
    asm volatile("st.release.gpu.u32 [%0], %1;" :: "l"(p), "r"(v) : "memory");
}
__device__ __forceinline__ void cluster_sync_all() {
    asm volatile("barrier.cluster.arrive.aligned;" ::: "memory");
    asm volatile("barrier.cluster.wait.aligned;" ::: "memory");
}
__device__ __forceinline__ void mma_f16(float* d, const uint4& a,
                                        unsigned b0, unsigned b1) {
    asm volatile(
        "mma.sync.aligned.m16n8k16.row.col.f32.f16.f16.f32 "
        "{%0,%1,%2,%3},{%4,%5,%6,%7},{%8,%9},{%0,%1,%2,%3};"
        : "+f"(d[0]), "+f"(d[1]), "+f"(d[2]), "+f"(d[3])
        : "r"(a.x), "r"(a.y), "r"(a.z), "r"(a.w), "r"(b0), "r"(b1));
}
__device__ __forceinline__ void st16cg(void* p, unsigned short v) {
    asm volatile("st.global.cg.b16 [%0], %1;" :: "l"(p), "h"(v) : "memory");
}

// =================================================================
// counter-zero kernels (run at start of every launch / graph replay)
// =================================================================
__global__ void zero_cnt_kernel() {
    if (threadIdx.x < NCHUNK) g_cnt_xg1[threadIdx.x] = 0;
}
__global__ void zero_wm_kernel() {
    if (threadIdx.x < 16) g_wm_h1[threadIdx.x] = 0;
}

// =================================================================
// Weight/bias permutation + fp16 hi/scaled-lo split for W_hh
// =================================================================
__global__ void prep_kernel(const float* __restrict__ Whh0,
                            const float* __restrict__ Whh1,
                            const float* __restrict__ Wih0,
                            const float* __restrict__ Wih1,
                            const float* __restrict__ bih0,
                            const float* __restrict__ bhh0,
                            const float* __restrict__ bih1,
                            const float* __restrict__ bhh1)
{
    int p = blockIdx.x;                   // permuted row 0..1023
    int src = (p & 3) * HSZ + (p >> 2);   // gate = p&3, hcol = p>>2
    int tid = threadIdx.x;
    for (int k = tid; k < HSZ; k += blockDim.x) {
        float v0 = Whh0[src * HSZ + k];
        __half a0 = __float2half_rn(v0);
        g_W1_0[p * HSZ + k] = a0;
        g_W2_0[p * HSZ + k] = __float2half_rn((v0 - __half2float(a0)) * 2048.f);
        float v1 = Whh1[src * HSZ + k];
        __half a1 = __float2half_rn(v1);
        g_W1_1[p * HSZ + k] = a1;
        g_W2_1[p * HSZ + k] = __float2half_rn((v1 - __half2float(a1)) * 2048.f);
        g_Wp_ih1[p * HSZ + k] = Wih1[src * HSZ + k];
    }
    for (int k = tid; k < NIN; k += blockDim.x)
        g_Wp_ih0[p * NIN + k] = Wih0[src * NIN + k];
    if (tid == 0) {
        g_bp0[p] = bih0[src] + bhh0[src];
        g_bp1[p] = bih1[src] + bhh1[src];
    }
}

// =================================================================
// MV[m][h] = sum_h' mem_vals[m][h'] * W_out[h][256 + h']
// =================================================================
__global__ void mv_kernel(const float* __restrict__ vals,
                          const float* __restrict__ Wout,
                          float* __restrict__ mv)
{
    int m = blockIdx.x, h = threadIdx.x;
    const float* vrow = vals + (size_t)m * HSZ;
    const float* wrow = Wout + (size_t)h * 2 * HSZ + HSZ;
    float acc = 0.f;
#pragma unroll 8
    for (int k = 0; k < HSZ; k++) acc = fmaf(vrow[k], wrow[k], acc);
    mv[(size_t)m * HSZ + h] = acc;
}

// =================================================================
// Standalone tiled SIMT GEMM (used for xg0, full grid, sequential):
//   C[m,n] = sum_k A[m,k]*B[n,k] + bias[n]
// =================================================================
__global__ __launch_bounds__(256) void gemm_bt_kernel(
    const float* __restrict__ A, int lda,
    const float* __restrict__ B, int ldb,
    float* __restrict__ C, int ldc,
    int K,
    const float* __restrict__ bias1)
{
    __shared__ __align__(16) float As[16][68];
    __shared__ __align__(16) float Bs[16][68];
    int tid = threadIdx.x;
    int bm = blockIdx.y * 64, bn = blockIdx.x * 64;
    int lr = tid >> 2, lk = (tid & 3) * 4;
    int tx = tid & 15, ty = tid >> 4;
    float acc[4][4] = {};
    const float* Ap = A + (size_t)(bm + lr) * lda + lk;
    const float* Bp = B + (size_t)(bn + lr) * ldb + lk;

    for (int k0 = 0; k0 < K; k0 += 16) {
        float4 av = *(const float4*)(Ap + k0);
        float4 bv = *(const float4*)(Bp + k0);
        As[lk + 0][lr] = av.x; As[lk + 1][lr] = av.y;
        As[lk + 2][lr] = av.z; As[lk + 3][lr] = av.w;
        Bs[lk + 0][lr] = bv.x; Bs[lk + 1][lr] = bv.y;
        Bs[lk + 2][lr] = bv.z; Bs[lk + 3][lr] = bv.w;
        __syncthreads();
#pragma unroll
        for (int kk = 0; kk < 16; kk++) {
            float4 a4 = *(const float4*)&As[kk][ty * 4];
            float4 b4 = *(const float4*)&Bs[kk][tx * 4];
            float a[4] = {a4.x, a4.y, a4.z, a4.w};
            float b[4] = {b4.x, b4.y, b4.z, b4.w};
#pragma unroll
            for (int i = 0; i < 4; i++)
#pragma unroll
                for (int j = 0; j < 4; j++)
                    acc[i][j] = fmaf(a[i], b[j], acc[i][j]);
        }
        __syncthreads();
    }

    float bcol[4];
#pragma unroll
    for (int j = 0; j < 4; j++)
        bcol[j] = bias1 ? bias1[bn + tx * 4 + j] : 0.f;
#pragma unroll
    for (int i = 0; i < 4; i++) {
        int m = bm + ty * 4 + i;
        float4 o;
        o.x = acc[i][0] + bcol[0];
        o.y = acc[i][1] + bcol[1];
        o.z = acc[i][2] + bcol[2];
        o.w = acc[i][3] + bcol[3];
        *(float4*)&C[(size_t)m * ldc + bn + tx * 4] = o;
    }
}

// =================================================================
// Worker GEMM tile: one 64x64 tile of a 16-token xg1 chunk.
//   rows: m = b*16 + ti -> token b*SLEN + chunk*16 + ti
// =================================================================
__device__ void worker_tile(int chunk, int mtile, int ntile)
{
    __shared__ __align__(16) float As[16][68];
    __shared__ __align__(16) float Bs[16][68];
    int tid = threadIdx.x;
    int lr = tid >> 2, lk = (tid & 3) * 4;
    int tx = tid & 15, ty = tid >> 4;
    int mrow = mtile * 64 + lr;
    int b = mrow >> 4, ti = mrow & 15;
    const float* Ap = g_h + ((size_t)b * SLEN + chunk * 16 + ti) * HSZ + lk;
    const float* Bp = g_Wp_ih1 + (size_t)(ntile * 64 + lr) * HSZ + lk;
    float acc[4][4] = {};

    for (int k0 = 0; k0 < HSZ; k0 += 16) {
        float4 av = *(const float4*)(Ap + k0);
        float4 bv = *(const float4*)(Bp + k0);
        As[lk + 0][lr] = av.x; As[lk + 1][lr] = av.y;
        As[lk + 2][lr] = av.z; As[lk + 3][lr] = av.w;
        Bs[lk + 0][lr] = bv.x; Bs[lk + 1][lr] = bv.y;
        Bs[lk + 2][lr] = bv.z; Bs[lk + 3][lr] = bv.w;
        __syncthreads();
#pragma unroll
        for (int kk = 0; kk < 16; kk++) {
            float4 a4 = *(const float4*)&As[kk][ty * 4];
            float4 b4 = *(const float4*)&Bs[kk][tx * 4];
            float a[4] = {a4.x, a4.y, a4.z, a4.w};
            float bb[4] = {b4.x, b4.y, b4.z, b4.w};
#pragma unroll
            for (int i = 0; i < 4; i++)
#pragma unroll
                for (int j = 0; j < 4; j++)
                    acc[i][j] = fmaf(a[i], bb[j], acc[i][j]);
        }
        __syncthreads();
    }

    int bn = ntile * 64;
    float bcol[4];
#pragma unroll
    for (int j = 0; j < 4; j++) bcol[j] = g_bp1[bn + tx * 4 + j];
#pragma unroll
    for (int i = 0; i < 4; i++) {
        int mr = mtile * 64 + ty * 4 + i;
        int b2 = mr >> 4, t2 = mr & 15;
        size_t row = (size_t)b2 * SLEN + chunk * 16 + t2;
        float4 o;
        o.x = acc[i][0] + bcol[0];
        o.y = acc[i][1] + bcol[1];
        o.z = acc[i][2] + bcol[2];
        o.w = acc[i][3] + bcol[3];
        *(float4*)&g_xg1[row * G4 + bn + tx * 4] = o;
    }
}

// =================================================================
// Worker body: stream xg1 chunk-by-chunk, gated on the h1 watermark.
// =================================================================
__device__ void worker_body(int wkr)
{
    int tid = threadIdx.x;
    for (int c = 0; c < NCHUNK; c++) {
        if (tid == 0) {                       // wait for h1 chunk c
            int need = (c + 1) * 16;
            for (;;) {
                int mn = 0x7fffffff;
#pragma unroll
                for (int i = 0; i < 16; i++) {
                    int v = ld_acq(&g_wm_h1[i]);
                    mn = v < mn ? v : mn;
                }
                if (mn >= need) break;
                __nanosleep(128);
            }
        }
        __syncthreads();
        int done = 0;
        for (int tile = wkr; tile < NTILES; tile += NWORK) {
            worker_tile(c, tile >> 4, tile & 15);
            done++;
        }
        __syncthreads();
        __threadfence();
        if (tid == 0) atomicAdd(&g_cnt_xg1[c], done);
    }
}

// =================================================================
// Scan body (R8-validated exact 2x2-piece fp16 MMA). role 0 reads
// precomputed xg0 freely and publishes the h1 watermark; role 1
// polls per-chunk xg1 completion counters.
// =================================================================
__device__ void scan_body(int bid, int role)
{
    const float*  xg = role ? g_xg1 : g_xg0;
    const __half* W1 = role ? g_W1_1 : g_W1_0;
    const __half* W2 = role ? g_W2_1 : g_W2_0;
    float* hout = role ? g_h2 : g_h;

    int tid = threadIdx.x;
    int lane = tid & 31, w = tid >> 5;
    int crank = bid & 7, cid = (bid >> 3) & 1;
    int lane4 = lane & 3, laneq = lane >> 2;

    // ---- stationary weight fragments: 2 ntiles x 16 ktiles x 2 regs ----
    unsigned w1r[2][16][2], w2r[2][16][2];
#pragma unroll
    for (int p = 0; p < 2; p++) {
        int n_g = crank * 128 + w * 16 + p * 8 + laneq;   // permuted gate row
        const unsigned* r1 = (const unsigned*)(W1 + (size_t)n_g * HSZ);
        const unsigned* r2 = (const unsigned*)(W2 + (size_t)n_g * HSZ);
#pragma unroll
        for (int kt = 0; kt < 16; kt++) {
            w1r[p][kt][0] = __ldg(r1 + kt * 8 + lane4);
            w1r[p][kt][1] = __ldg(r1 + kt * 8 + 4 + lane4);
            w2r[p][kt][0] = __ldg(r2 + kt * 8 + lane4);
            w2r[p][kt][1] = __ldg(r2 + kt * 8 + 4 + lane4);
        }
    }

    // ---- stage pointers + zero init (h_prev = 0) ----
    float* stg = g_hstage + (size_t)(role * 2 + cid) * 8192;
    for (int i = crank * 1024 + tid; i < (crank + 1) * 1024; i += 256)
        __stcg(stg + i, 0.f);

    // ---- epilogue role: (batch, hcol) per ntile ----
    bool odd = (lane & 1) != 0;
    int b_loc = laneq + (odd ? 8 : 0);
    int b_glob = cid * 16 + b_loc;
    int hcl[2];
    hcl[0] = w * 4 + (lane4 >> 1);
    hcl[1] = hcl[0] + 2;
    const float* xgp[2];
    float* hop[2];
    unsigned soff[2];
#pragma unroll
    for (int p = 0; p < 2; p++) {
        xgp[p] = xg + ((size_t)b_glob * SLEN) * G4 + crank * 128 + hcl[p] * 4;
        hop[p] = hout + ((size_t)b_glob * SLEN) * HSZ + crank * 32 + hcl[p];
        int k = crank * 32 + hcl[p];
        int kt = k >> 4, kin = k & 15, c = kin >> 1, half = kin & 1;
        int word = (c < 4 ? 0 : 2) + (b_loc < 8 ? 0 : 1);
        int lane_s = (b_loc & 7) * 4 + (c & 3);
        soff[p] = (unsigned)((((kt * 32 + lane_s) * 4 + word) * 2 + half));
    }
    float cst[2] = {0.f, 0.f};

    cluster_sync_all();   // stages zeroed cluster-wide

    const float S1 = 4.8828125e-4f;          // 2^-11

    for (int t = 0; t < SLEN; t++) {
        // ---- layer-1 only: chunk-granular xg1 availability poll ----
        if (role == 1 && (t & 15) == 0) {
            if (tid == 0) {
                int c = t >> 4;
                while (ld_acq(&g_cnt_xg1[c]) < NTILES) __nanosleep(128);
            }
            __syncthreads();
        }

        int par = t & 1;
        const uint4* s1 = (const uint4*)(stg + par * 2048);
        const uint4* s2 = (const uint4*)(stg + 4096 + par * 2048);
        unsigned short* d1 = (unsigned short*)(stg + (par ^ 1) * 2048);
        unsigned short* d2 = (unsigned short*)(stg + 4096 + (par ^ 1) * 2048);

        float4 xv0 = *(const float4*)(xgp[0] + (size_t)t * G4);
        float4 xv1 = *(const float4*)(xgp[1] + (size_t)t * G4);

        uint4 a1[4], a2[4];
#pragma unroll
        for (int i = 0; i < 4; i++) {
            a1[i] = __ldcg(s1 + i * 32 + lane);
            a2[i] = __ldcg(s2 + i * 32 + lane);
        }

        float A0[4] = {}, A1v[4] = {}, B0[4] = {}, B1v[4] = {};
        float C0[4] = {}, C1v[4] = {};
#pragma unroll
        for (int kt = 0; kt < 16; kt++) {
            uint4 x1 = a1[kt & 3], x2 = a2[kt & 3];
            if (kt + 4 < 16) {
                a1[kt & 3] = __ldcg(s1 + (kt + 4) * 32 + lane);
                a2[kt & 3] = __ldcg(s2 + (kt + 4) * 32 + lane);
            }
            mma_f16(A0,  x1, w1r[0][kt][0], w1r[0][kt][1]);
            mma_f16(A1v, x1, w1r[1][kt][0], w1r[1][kt][1]);
            mma_f16(B0,  x2, w1r[0][kt][0], w1r[0][kt][1]);
            mma_f16(B1v, x2, w1r[1][kt][0], w1r[1][kt][1]);
            mma_f16(B0,  x1, w2r[0][kt][0], w2r[0][kt][1]);
            mma_f16(B1v, x1, w2r[1][kt][0], w2r[1][kt][1]);
            mma_f16(C0,  x2, w2r[0][kt][0], w2r[0][kt][1]);
            mma_f16(C1v, x2, w2r[1][kt][0], w2r[1][kt][1]);
        }

#pragma unroll
        for (int p = 0; p < 2; p++) {
            float* A = p ? A1v : A0;
            float* B = p ? B1v : B0;
            float* C = p ? C1v : C0;
            float g4[4];
#pragma unroll
            for (int i = 0; i < 4; i++)
                g4[i] = fmaf(S1, fmaf(S1, C[i], B[i]), A[i]);
            float e0 = __shfl_xor_sync(0xffffffffu, g4[0], 1);
            float e1 = __shfl_xor_sync(0xffffffffu, g4[1], 1);
            float e2 = __shfl_xor_sync(0xffffffffu, g4[2], 1);
            float e3 = __shfl_xor_sync(0xffffffffu, g4[3], 1);
            float gi, gf, gg, go;
            if (!odd) { gi = g4[0]; gf = g4[1]; gg = e0; go = e1; }
            else      { gi = e2;   gf = e3;   gg = g4[2]; go = g4[3]; }
            float4 xv = p ? xv1 : xv0;
            gi += xv.x; gf += xv.y; gg += xv.z; go += xv.w;
            float si = 1.f / (1.f + expf(-gi));
            float sf = 1.f / (1.f + expf(-gf));
            float so = 1.f / (1.f + expf(-go));
            float tg = tanhf(gg);
            cst[p] = fmaf(sf, cst[p], si * tg);
            float h = so * tanhf(cst[p]);
            hop[p][(size_t)t * HSZ] = h;
            __half h1 = __float2half_rn(h);
            float r = (h - __half2float(h1)) * 2048.f;
            __half h2 = __float2half_rn(r);
            st16cg(d1 + soff[p], __half_as_ushort(h1));
            st16cg(d2 + soff[p], __half_as_ushort(h2));
        }
        cluster_sync_all();   // release h stores / acquire peers' stage

        // ---- publish h1 watermark (layer 0 only), every 16 steps ----
        if (role == 0 && (t & 15) == 15 && tid == 0) {
            __threadfence();
            st_rel(&g_wm_h1[cid * 8 + crank], t + 1);
        }
    }
}

// =================================================================
// Mega kernel: 12 clusters / 96 CTAs (within ~14-cluster residency
// envelope). Clusters 0-1 = layer-0 scan, 2-3 = layer-1 scan,
// 4-11 = xg1 streaming workers.
// =================================================================
__global__ __launch_bounds__(256, 1) __cluster_dims__(8, 1, 1)
void fused_pipeline()
{
    int bid = blockIdx.x;
    if (bid < 32) scan_body(bid & 15, bid >> 4);
    else          worker_body(bid - 32);
}

// =================================================================
// kNN over quantum memory: per token -> 3 indices + 3 scaled weights
// =================================================================
__global__ __launch_bounds__(256) void knn_kernel(
    const float* __restrict__ lstm,
    const float* __restrict__ Wcq, const float* __restrict__ bcq,
    const float* __restrict__ keys, const float* __restrict__ qwp,
    float* __restrict__ wout, int* __restrict__ idxout)
{
    __shared__ float sWcq[QDIM][HSZ];
    __shared__ float skn[MMEM][QDIM];
    __shared__ __align__(16) float sh[8][HSZ];
    __shared__ float sq[8][QDIM];
    __shared__ float ssims[8][MMEM];
    int tid = threadIdx.x;
    for (int i = tid; i < QDIM * HSZ; i += 256)
        sWcq[i >> 8][i & 255] = Wcq[i];
    if (tid < MMEM) {
        float kv[QDIM]; float nrm = 0.f;
#pragma unroll
        for (int d = 0; d < QDIM; d++) { kv[d] = keys[tid * QDIM + d]; nrm += kv[d] * kv[d]; }
        float inv = 1.f / (sqrtf(nrm) + 1e-8f);
#pragma unroll
        for (int d = 0; d < QDIM; d++) skn[tid][d] = kv[d] * inv;
    }
    __syncthreads();

    int wid = tid >> 5, lane = tid & 31;
    int token = blockIdx.x * 8 + wid;
    const float* hrow = lstm + (size_t)token * HSZ;
    for (int i = lane; i < HSZ / 4; i += 32)
        ((float4*)sh[wid])[i] = ((const float4*)hrow)[i];
    __syncwarp();
    if (lane < QDIM) {
        float acc = bcq[lane];
#pragma unroll 8
        for (int k = 0; k < HSZ; k++) acc = fmaf(sWcq[lane][k], sh[wid][k], acc);
        sq[wid][lane] = tanhf(acc);
    }
    __syncwarp();
    float qn[QDIM];
    {
        float nrm = 0.f;
#pragma unroll
        for (int d = 0; d < QDIM; d++) { float v = sq[wid][d]; nrm += v * v; }
        float inv = 1.f / (sqrtf(nrm) + 1e-8f);
#pragma unroll
        for (int d = 0; d < QDIM; d++) qn[d] = sq[wid][d] * inv;
    }
#pragma unroll
    for (int mm = 0; mm < 2; mm++) {
        int m = lane + mm * 32;
        float s = 0.f;
#pragma unroll
        for (int d = 0; d < QDIM; d++) s = fmaf(qn[d], skn[m][d], s);
        ssims[wid][m] = s;
    }
    __syncwarp();
    if (lane == 0) {
        float v0 = -1e30f, v1 = -1e30f, v2 = -1e30f;
        int i0 = 0, i1 = 0, i2 = 0;
        for (int m = 0; m < MMEM; m++) {
            float s = ssims[wid][m];
            if (s > v0)      { v2 = v1; i2 = i1; v1 = v0; i1 = i0; v0 = s; i0 = m; }
            else if (s > v1) { v2 = v1; i2 = i1; v1 = s;  i1 = m; }
            else if (s > v2) { v2 = s;  i2 = m; }
        }
        float tot = v0 + v1 + v2;
        float qw = *qwp;
        float sc = (tot > 0.f) ? (qw / tot) : 0.f;
        wout[token * 4 + 0] = v0 * sc;
        wout[token * 4 + 1] = v1 * sc;
        wout[token * 4 + 2] = v2 * sc;
        idxout[token * 4 + 0] = i0;
        idxout[token * 4 + 1] = i1;
        idxout[token * 4 + 2] = i2;
    }
}

// =================================================================
// Output GEMM with fused quantum-memory epilogue
// =================================================================
__global__ __launch_bounds__(256) void out_gemm_kernel(
    const float* __restrict__ A, int lda,
    const float* __restrict__ B, int ldb,
    float* __restrict__ C, int ldc,
    int K,
    const float* __restrict__ bout,
    const float* __restrict__ cwp,
    const float* __restrict__ wts,
    const int*   __restrict__ idxs,
    const float* __restrict__ MV)
{
    __shared__ __align__(16) float As[16][68];
    __shared__ __align__(16) float Bs[16][68];
    int tid = threadIdx.x;
    int bm = blockIdx.y * 64, bn = blockIdx.x * 64;
    int lr = tid >> 2, lk = (tid & 3) * 4;
    int tx = tid & 15, ty = tid >> 4;
    float acc[4][4] = {};
    const float* Ap = A + (size_t)(bm + lr) * lda + lk;
    const float* Bp = B + (size_t)(bn + lr) * ldb + lk;

    for (int k0 = 0; k0 < K; k0 += 16) {
        float4 av = *(const float4*)(Ap + k0);
        float4 bv = *(const float4*)(Bp + k0);
        As[lk + 0][lr] = av.x; As[lk + 1][lr] = av.y;
        As[lk + 2][lr] = av.z; As[lk + 3][lr] = av.w;
        Bs[lk + 0][lr] = bv.x; Bs[lk + 1][lr] = bv.y;
        Bs[lk + 2][lr] = bv.z; Bs[lk + 3][lr] = bv.w;
        __syncthreads();
#pragma unroll
        for (int kk = 0; kk < 16; kk++) {
            float4 a4 = *(const float4*)&As[kk][ty * 4];
            float4 b4 = *(const float4*)&Bs[kk][tx * 4];
            float a[4] = {a4.x, a4.y, a4.z, a4.w};
            float b[4] = {b4.x, b4.y, b4.z, b4.w};
#pragma unroll
            for (int i = 0; i < 4; i++)
#pragma unroll
                for (int j = 0; j < 4; j++)
                    acc[i][j] = fmaf(a[i], b[j], acc[i][j]);
        }
        __syncthreads();
    }

    float cw = *cwp;
#pragma unroll
    for (int i = 0; i < 4; i++) {
        int m = bm + ty * 4 + i;
        float w0 = wts[m * 4 + 0], w1 = wts[m * 4 + 1], w2 = wts[m * 4 + 2];
        int   i0 = idxs[m * 4 + 0], i1 = idxs[m * 4 + 1], i2 = idxs[m * 4 + 2];
        const float* mv0 = MV + (size_t)i0 * HSZ;
        const float* mv1 = MV + (size_t)i1 * HSZ;
        const float* mv2 = MV + (size_t)i2 * HSZ;
        float out4[4];
#pragma unroll
        for (int j = 0; j < 4; j++) {
            int n = bn + tx * 4 + j;
            float v = cw * acc[i][j] + bout[n];
            v = fmaf(w0, mv0[n], v);
            v = fmaf(w1, mv1[n], v);
            v = fmaf(w2, mv2[n], v);
            out4[j] = v;
        }
        *(float4*)&C[(size_t)m * ldc + bn + tx * 4] =
            make_float4(out4[0], out4[1], out4[2], out4[3]);
    }
}

// =================================================================
extern "C" void kernel_launch(void* const* d_in, const int* in_sizes, int n_in,
                              void* d_out, int out_size) {
    const float* x      = (const float*)d_in[0];
    const float* W_ih0  = (const float*)d_in[1];
    const float* W_hh0  = (const float*)d_in[2];
    const float* b_ih0  = (const float*)d_in[3];
    const float* b_hh0  = (const float*)d_in[4];
    const float* W_ih1  = (const float*)d_in[5];
    const float* W_hh1  = (const float*)d_in[6];
    const float* b_ih1  = (const float*)d_in[7];
    const float* b_hh1  = (const float*)d_in[8];
    const float* W_cq   = (const float*)d_in[9];
    const float* b_cq   = (const float*)d_in[10];
    const float* mkeys  = (const float*)d_in[11];
    const float* mvals  = (const float*)d_in[12];
    const float* W_out  = (const float*)d_in[13];
    const float* b_out  = (const float*)d_in[14];
    const float* cw     = (const float*)d_in[15];
    const float* qw     = (const float*)d_in[16];
    float* out = (float*)d_out;

    float* xg0  = nullptr; cudaGetSymbolAddress((void**)&xg0,  g_xg0);
    float* hbf2 = nullptr; cudaGetSymbolAddress((void**)&hbf2, g_h2);
    float* mv   = nullptr; cudaGetSymbolAddress((void**)&mv,   g_mv);
    float* wts  = nullptr; cudaGetSymbolAddress((void**)&wts,  g_w);
    int*   idx  = nullptr; cudaGetSymbolAddress((void**)&idx,  g_idx);
    float* Wpi0 = nullptr; cudaGetSymbolAddress((void**)&Wpi0, g_Wp_ih0);
    float* bp0  = nullptr; cudaGetSymbolAddress((void**)&bp0,  g_bp0);

    // #1-#2 zero pipeline counters (graph-replay safe)
    zero_cnt_kernel<<<1, 256>>>();
    zero_wm_kernel<<<1, 32>>>();

    // #3 permute weights/biases + fp16 split of W_hh
    prep_kernel<<<G4, 256>>>(W_hh0, W_hh1, W_ih0, W_ih1,
                             b_ih0, b_hh0, b_ih1, b_hh1);
    // #4
    mv_kernel<<<MMEM, HSZ>>>(mvals, W_out, mv);

    // #5 xg0 = x @ Wp_ih0^T + bias (sequential, no deps)
    {
        dim3 grid(G4 / 64, NTOK / 64);
        gemm_bt_kernel<<<grid, 256>>>(x, NIN, Wpi0, NIN, xg0, G4, NIN, bp0);
    }

    // #6 fused pipeline: both scans + streaming xg1 workers (ncu slot)
    fused_pipeline<<<96, 256>>>();

    // #7 kNN metadata
    knn_kernel<<<NTOK / 8, 256>>>(hbf2, W_cq, b_cq, mkeys, qw, wts, idx);

    // #8 out = cw*(lstm@Wc^T) + b_out + sum_k w_k*MV[idx_k]
    {
        dim3 grid(HSZ / 64, NTOK / 64);
        out_gemm_kernel<<<grid, 256>>>(hbf2, HSZ, W_out, 2 * HSZ, out, HSZ, HSZ,
                                       b_out, cw, wts, idx, mv);
    }
}